// round 2
// baseline (speedup 1.0000x reference)
#include <cuda_runtime.h>
#include <cuda_bf16.h>

// ============================================================================
// ChebNet: 3x ChebConv(K=5) + FC, N=100000 nodes, E=1.6M edges, HID=64.
//   1. Preprocess per launch: degree + dst-histogram, exclusive scan -> CSR
//      row_ptr, counting-sort edges by dst. No atomics in hot prop loops.
//   2. Layer 1 (Fin=1): scalar Chebyshev recurrence t_k [N], then one combine
//      kernel producing H = relu(sum_k t_k * W1[k] + b1)  [N,64].
//   3. Layers 2,3 (Fin=64): warp-per-node fused kernels:
//        gemm_bias:  out = H @ W[0] + b
//        prop_fused: Tx_k = 2*prop(Tin) - Tprev;  out += Tx_k @ W[k]
//   4. FC: warp-per-node dot product.
// edge_index arrives as int32 (harness downcasts int64 inputs).
// ============================================================================

#define FULLMASK 0xffffffffu

static constexpr int NMAX = 131072;
static constexpr int EMAX = 2000000;
static constexpr int NBMAX = 128;      // scan blocks: NMAX/1024

// ---- static device scratch (allocation-free rule) ----
__device__ int   g_deg[NMAX];
__device__ int   g_cnt[NMAX];
__device__ float g_dinv[NMAX];
__device__ int   g_rp[NMAX + 1];
__device__ int   g_cursor[NMAX];
__device__ int   g_bsum[NBMAX];
__device__ int   g_boff[NBMAX];
__device__ int   g_ssrc[EMAX];
__device__ float g_snorm[EMAX];
__device__ float g_t1[NMAX], g_t2[NMAX], g_t3[NMAX], g_t4[NMAX];
__device__ float g_X0[NMAX * 64];
__device__ float g_X1[NMAX * 64];
__device__ float g_X2[NMAX * 64];
__device__ float g_OUT[NMAX * 64];

// ============================================================================
// Preprocessing
// ============================================================================

__global__ void deg_hist_kernel(const int* __restrict__ ei, int E,
                                int* __restrict__ deg, int* __restrict__ cnt) {
    int e = blockIdx.x * blockDim.x + threadIdx.x;
    if (e < E) {
        int s = ei[e];
        int d = ei[E + e];
        atomicAdd(&deg[s], 1);
        atomicAdd(&cnt[d], 1);
    }
}

__global__ void dinv_kernel(const int* __restrict__ deg, float* __restrict__ dinv, int N) {
    int n = blockIdx.x * blockDim.x + threadIdx.x;
    if (n < N) {
        int d = deg[n];
        dinv[n] = (d > 0) ? rsqrtf((float)d) : 0.0f;
    }
}

// Block-level exclusive scan of cnt (1024 elements / block).
__global__ void scan_blocks_kernel(const int* __restrict__ cnt, int* __restrict__ rp,
                                   int* __restrict__ bsum, int N) {
    __shared__ int s[1024];
    int idx = blockIdx.x * 1024 + threadIdx.x;
    int v = (idx < N) ? cnt[idx] : 0;
    s[threadIdx.x] = v;
    __syncthreads();
    for (int off = 1; off < 1024; off <<= 1) {
        int t = (threadIdx.x >= off) ? s[threadIdx.x - off] : 0;
        __syncthreads();
        s[threadIdx.x] += t;
        __syncthreads();
    }
    if (idx < N) rp[idx] = s[threadIdx.x] - v;   // exclusive
    if (threadIdx.x == 1023) bsum[blockIdx.x] = s[1023];
}

__global__ void scan_top_kernel(const int* __restrict__ bsum, int* __restrict__ boff,
                                int nb, int* __restrict__ rp, int N) {
    if (blockIdx.x == 0 && threadIdx.x == 0) {
        int run = 0;
        for (int b = 0; b < nb; ++b) { boff[b] = run; run += bsum[b]; }
        rp[N] = run;   // == E
    }
}

__global__ void scan_add_kernel(int* __restrict__ rp, int* __restrict__ cursor,
                                const int* __restrict__ boff, int N) {
    int idx = blockIdx.x * 1024 + threadIdx.x;
    if (idx < N) {
        int r = rp[idx] + boff[blockIdx.x];
        rp[idx] = r;
        cursor[idx] = r;
    }
}

__global__ void scatter_kernel(const int* __restrict__ ei, int E,
                               const float* __restrict__ dinv,
                               int* __restrict__ cursor,
                               int* __restrict__ ssrc, float* __restrict__ snorm) {
    int e = blockIdx.x * blockDim.x + threadIdx.x;
    if (e < E) {
        int s = ei[e];
        int d = ei[E + e];
        float nm = -(dinv[s] * dinv[d]);
        int pos = atomicAdd(&cursor[d], 1);
        ssrc[pos] = s;
        snorm[pos] = nm;
    }
}

// ============================================================================
// Layer 1 (scalar features)
// ============================================================================

template <bool USE_PREV>
__global__ void scalar_prop_kernel(const float* __restrict__ tin,
                                   const float* __restrict__ tprev,
                                   float* __restrict__ tout,
                                   const int* __restrict__ rp,
                                   const int* __restrict__ ssrc,
                                   const float* __restrict__ snorm, int N) {
    int n = blockIdx.x * blockDim.x + threadIdx.x;
    if (n >= N) return;
    float acc = 0.0f;
    int e1 = rp[n + 1];
    #pragma unroll 4
    for (int e = rp[n]; e < e1; ++e)
        acc += tin[ssrc[e]] * snorm[e];
    tout[n] = USE_PREV ? (2.0f * acc - tprev[n]) : acc;
}

// H[n][j] = relu( b1[j] + sum_k t_k[n] * W1[k*64 + j] )
__global__ void combine1_kernel(const float* __restrict__ x,
                                const float* __restrict__ t1, const float* __restrict__ t2,
                                const float* __restrict__ t3, const float* __restrict__ t4,
                                const float* __restrict__ W1, const float* __restrict__ b1,
                                float* __restrict__ H, int N) {
    int tid = blockIdx.x * blockDim.x + threadIdx.x;
    int n = tid >> 5;
    int l = tid & 31;
    if (n >= N) return;
    float v0 = __ldg(&x[n]),  v1 = __ldg(&t1[n]), v2 = __ldg(&t2[n]);
    float v3 = __ldg(&t3[n]), v4 = __ldg(&t4[n]);
    int j = 2 * l;
    float2 o  = *(const float2*)&b1[j];
    float2 w0 = *(const float2*)&W1[0 * 64 + j];
    float2 w1 = *(const float2*)&W1[1 * 64 + j];
    float2 w2 = *(const float2*)&W1[2 * 64 + j];
    float2 w3 = *(const float2*)&W1[3 * 64 + j];
    float2 w4 = *(const float2*)&W1[4 * 64 + j];
    o.x += v0 * w0.x + v1 * w1.x + v2 * w2.x + v3 * w3.x + v4 * w4.x;
    o.y += v0 * w0.y + v1 * w1.y + v2 * w2.y + v3 * w3.y + v4 * w4.y;
    o.x = fmaxf(o.x, 0.0f);
    o.y = fmaxf(o.y, 0.0f);
    ((float2*)H)[n * 32 + l] = o;
}

// ============================================================================
// Layers 2/3: warp-per-node fused kernels (Fin = Fout = 64)
// ============================================================================

// out[n] = b + H[n] @ W     (64x64, W in shared, shfl-broadcast GEMM)
__global__ void gemm_bias_kernel(const float* __restrict__ H,
                                 const float* __restrict__ W,
                                 const float* __restrict__ b,
                                 float* __restrict__ out, int N) {
    __shared__ float Ws[4096];
    __shared__ float Bs[64];
    for (int i = threadIdx.x; i < 4096; i += blockDim.x) Ws[i] = W[i];
    if (threadIdx.x < 64) Bs[threadIdx.x] = b[threadIdx.x];
    __syncthreads();
    int warp = threadIdx.x >> 5, lane = threadIdx.x & 31;
    int wpb = blockDim.x >> 5;
    for (int n = blockIdx.x * wpb + warp; n < N; n += gridDim.x * wpb) {
        float2 h = ((const float2*)H)[n * 32 + lane];
        float2 o = make_float2(Bs[2 * lane], Bs[2 * lane + 1]);
        #pragma unroll
        for (int sl = 0; sl < 32; ++sl) {
            float a0 = __shfl_sync(FULLMASK, h.x, sl);
            float a1 = __shfl_sync(FULLMASK, h.y, sl);
            float2 w0 = *(const float2*)&Ws[(2 * sl) * 64 + 2 * lane];
            float2 w1 = *(const float2*)&Ws[(2 * sl + 1) * 64 + 2 * lane];
            o.x += a0 * w0.x + a1 * w1.x;
            o.y += a0 * w0.y + a1 * w1.y;
        }
        ((float2*)out)[n * 32 + lane] = o;
    }
}

// Tx = 2*prop(Tin) - (USE_PREV ? Tprev : 0);  outDst = outIn + Tx @ W (+relu)
template <bool USE_PREV, bool WRITE_TX, bool RELU>
__global__ void prop_fused_kernel(const float* __restrict__ Tin,
                                  const float* __restrict__ Tprev,
                                  float* __restrict__ Txout,
                                  const float* __restrict__ outIn,
                                  float* __restrict__ outDst,
                                  const float* __restrict__ W,
                                  const int* __restrict__ rp,
                                  const int* __restrict__ ssrc,
                                  const float* __restrict__ snorm, int N) {
    __shared__ float Ws[4096];
    for (int i = threadIdx.x; i < 4096; i += blockDim.x) Ws[i] = W[i];
    __syncthreads();
    int warp = threadIdx.x >> 5, lane = threadIdx.x & 31;
    int wpb = blockDim.x >> 5;
    const float2* Tin2 = (const float2*)Tin;
    for (int n = blockIdx.x * wpb + warp; n < N; n += gridDim.x * wpb) {
        int e0 = rp[n], e1 = rp[n + 1];
        float2 acc = make_float2(0.0f, 0.0f);
        #pragma unroll 4
        for (int e = e0; e < e1; ++e) {
            int s = __ldg(&ssrc[e]);
            float nm = __ldg(&snorm[e]);
            float2 v = Tin2[s * 32 + lane];
            acc.x += nm * v.x;
            acc.y += nm * v.y;
        }
        float2 tx;
        if (USE_PREV) {
            float2 p = ((const float2*)Tprev)[n * 32 + lane];
            tx.x = 2.0f * acc.x - p.x;
            tx.y = 2.0f * acc.y - p.y;
        } else {
            tx = acc;
        }
        if (WRITE_TX) ((float2*)Txout)[n * 32 + lane] = tx;
        float2 o = ((const float2*)outIn)[n * 32 + lane];
        #pragma unroll
        for (int sl = 0; sl < 32; ++sl) {
            float a0 = __shfl_sync(FULLMASK, tx.x, sl);
            float a1 = __shfl_sync(FULLMASK, tx.y, sl);
            float2 w0 = *(const float2*)&Ws[(2 * sl) * 64 + 2 * lane];
            float2 w1 = *(const float2*)&Ws[(2 * sl + 1) * 64 + 2 * lane];
            o.x += a0 * w0.x + a1 * w1.x;
            o.y += a0 * w0.y + a1 * w1.y;
        }
        if (RELU) { o.x = fmaxf(o.x, 0.0f); o.y = fmaxf(o.y, 0.0f); }
        ((float2*)outDst)[n * 32 + lane] = o;
    }
}

// ============================================================================
// FC head: y[n] = H[n] . Wfc + bfc
// ============================================================================

__global__ void fc_kernel(const float* __restrict__ H,
                          const float* __restrict__ Wfc,
                          const float* __restrict__ bfc,
                          float* __restrict__ out, int N) {
    int warp = threadIdx.x >> 5, lane = threadIdx.x & 31;
    int wpb = blockDim.x >> 5;
    float2 w = ((const float2*)Wfc)[lane];
    float bb = __ldg(bfc);
    for (int n = blockIdx.x * wpb + warp; n < N; n += gridDim.x * wpb) {
        float2 h = ((const float2*)H)[n * 32 + lane];
        float p = h.x * w.x + h.y * w.y;
        #pragma unroll
        for (int off = 16; off; off >>= 1)
            p += __shfl_xor_sync(FULLMASK, p, off);
        if (lane == 0) out[n] = p + bb;
    }
}

// ============================================================================
// Host launch
// ============================================================================

extern "C" void kernel_launch(void* const* d_in, const int* in_sizes, int n_in,
                              void* d_out, int out_size) {
    const float* x   = (const float*)d_in[0];
    const int*   ei  = (const int*)d_in[1];     // int32 (harness downcasts int64)
    const float* W1  = (const float*)d_in[2];
    const float* b1  = (const float*)d_in[3];
    const float* W2  = (const float*)d_in[4];
    const float* b2  = (const float*)d_in[5];
    const float* W3  = (const float*)d_in[6];
    const float* b3  = (const float*)d_in[7];
    const float* Wfc = (const float*)d_in[8];
    const float* bfc = (const float*)d_in[9];
    float* out = (float*)d_out;

    const int N = in_sizes[0];
    const int E = in_sizes[1] / 2;

    // Resolve static scratch addresses.
    int *deg, *cnt, *rp, *cursor, *bsum, *boff, *ssrc;
    float *dinv, *snorm, *t1, *t2, *t3, *t4, *X0, *X1, *X2, *OUT;
    cudaGetSymbolAddress((void**)&deg,   g_deg);
    cudaGetSymbolAddress((void**)&cnt,   g_cnt);
    cudaGetSymbolAddress((void**)&dinv,  g_dinv);
    cudaGetSymbolAddress((void**)&rp,    g_rp);
    cudaGetSymbolAddress((void**)&cursor,g_cursor);
    cudaGetSymbolAddress((void**)&bsum,  g_bsum);
    cudaGetSymbolAddress((void**)&boff,  g_boff);
    cudaGetSymbolAddress((void**)&ssrc,  g_ssrc);
    cudaGetSymbolAddress((void**)&snorm, g_snorm);
    cudaGetSymbolAddress((void**)&t1,    g_t1);
    cudaGetSymbolAddress((void**)&t2,    g_t2);
    cudaGetSymbolAddress((void**)&t3,    g_t3);
    cudaGetSymbolAddress((void**)&t4,    g_t4);
    cudaGetSymbolAddress((void**)&X0,    g_X0);
    cudaGetSymbolAddress((void**)&X1,    g_X1);
    cudaGetSymbolAddress((void**)&X2,    g_X2);
    cudaGetSymbolAddress((void**)&OUT,   g_OUT);

    const int EB = (E + 255) / 256;
    const int NB = (N + 255) / 256;
    const int nb1024 = (N + 1023) / 1024;
    const int PGRID = 1184;   // grid-stride grid for warp-per-node kernels

    // --- preprocess: CSR by dst ---
    cudaMemsetAsync(deg, 0, (size_t)N * sizeof(int), 0);
    cudaMemsetAsync(cnt, 0, (size_t)N * sizeof(int), 0);
    deg_hist_kernel<<<EB, 256>>>(ei, E, deg, cnt);
    dinv_kernel<<<NB, 256>>>(deg, dinv, N);
    scan_blocks_kernel<<<nb1024, 1024>>>(cnt, rp, bsum, N);
    scan_top_kernel<<<1, 32>>>(bsum, boff, nb1024, rp, N);
    scan_add_kernel<<<nb1024, 1024>>>(rp, cursor, boff, N);
    scatter_kernel<<<EB, 256>>>(ei, E, dinv, cursor, ssrc, snorm);

    // --- layer 1 (Fin=1) ---
    scalar_prop_kernel<false><<<NB, 256>>>(x,  nullptr, t1, rp, ssrc, snorm, N);
    scalar_prop_kernel<true ><<<NB, 256>>>(t1, x,       t2, rp, ssrc, snorm, N);
    scalar_prop_kernel<true ><<<NB, 256>>>(t2, t1,      t3, rp, ssrc, snorm, N);
    scalar_prop_kernel<true ><<<NB, 256>>>(t3, t2,      t4, rp, ssrc, snorm, N);
    combine1_kernel<<<(N * 32 + 255) / 256, 256>>>(x, t1, t2, t3, t4, W1, b1, X0, N);

    // --- layer 2: H = X0 -> H2 = X1 ---
    gemm_bias_kernel<<<PGRID, 256>>>(X0, W2, b2, OUT, N);
    prop_fused_kernel<false, true,  false><<<PGRID, 256>>>(X0, nullptr, X1, OUT, OUT, W2 + 1 * 4096, rp, ssrc, snorm, N);
    prop_fused_kernel<true,  true,  false><<<PGRID, 256>>>(X1, X0,      X2, OUT, OUT, W2 + 2 * 4096, rp, ssrc, snorm, N);
    prop_fused_kernel<true,  true,  false><<<PGRID, 256>>>(X2, X1,      X0, OUT, OUT, W2 + 3 * 4096, rp, ssrc, snorm, N);
    prop_fused_kernel<true,  false, true ><<<PGRID, 256>>>(X0, X2, nullptr, OUT, X1,  W2 + 4 * 4096, rp, ssrc, snorm, N);

    // --- layer 3: H = X1 -> H3 = X2 ---
    gemm_bias_kernel<<<PGRID, 256>>>(X1, W3, b3, OUT, N);
    prop_fused_kernel<false, true,  false><<<PGRID, 256>>>(X1, nullptr, X2, OUT, OUT, W3 + 1 * 4096, rp, ssrc, snorm, N);
    prop_fused_kernel<true,  true,  false><<<PGRID, 256>>>(X2, X1,      X0, OUT, OUT, W3 + 2 * 4096, rp, ssrc, snorm, N);
    prop_fused_kernel<true,  true,  false><<<PGRID, 256>>>(X0, X2,      X1, OUT, OUT, W3 + 3 * 4096, rp, ssrc, snorm, N);
    prop_fused_kernel<true,  false, true ><<<PGRID, 256>>>(X1, X0, nullptr, OUT, X2,  W3 + 4 * 4096, rp, ssrc, snorm, N);

    // --- FC head ---
    fc_kernel<<<PGRID, 256>>>(X2, Wfc, bfc, out, N);
}

// round 3
// speedup vs baseline: 1.0483x; 1.0483x over previous
#include <cuda_runtime.h>
#include <cuda_bf16.h>

// ============================================================================
// ChebNet: 3x ChebConv(K=5) + FC, N=100000, E=1.6M, HID=64.
// R3: half-warp-per-edge float4 gathers (2 edges in flight / warp), packed
// (src,norm) edge metadata, fused tail kernels (last prop of layer2 also does
// layer3's W[0] GEMM; last prop of layer3 does the FC head directly).
// ============================================================================

#define FULLMASK 0xffffffffu

static constexpr int NMAX = 131072;
static constexpr int EMAX = 2000000;
static constexpr int NBMAX = 128;

// ---- static device scratch ----
__device__ int   g_deg[NMAX];
__device__ int   g_cnt[NMAX];
__device__ float g_dinv[NMAX];
__device__ int   g_rp[NMAX + 1];
__device__ int   g_cursor[NMAX];
__device__ int   g_bsum[NBMAX];
__device__ int   g_boff[NBMAX];
__device__ int2  g_epack[EMAX];          // (src, norm-as-bits)
__device__ float g_t1[NMAX], g_t2[NMAX], g_t3[NMAX], g_t4[NMAX];
__device__ float g_X0[NMAX * 64];
__device__ float g_X1[NMAX * 64];
__device__ float g_X2[NMAX * 64];
__device__ float g_OUT[NMAX * 64];

// ============================================================================
// Preprocessing
// ============================================================================

__global__ void deg_hist_kernel(const int* __restrict__ ei, int E,
                                int* __restrict__ deg, int* __restrict__ cnt) {
    int e = blockIdx.x * blockDim.x + threadIdx.x;
    if (e < E) {
        atomicAdd(&deg[ei[e]], 1);
        atomicAdd(&cnt[ei[E + e]], 1);
    }
}

__global__ void dinv_kernel(const int* __restrict__ deg, float* __restrict__ dinv, int N) {
    int n = blockIdx.x * blockDim.x + threadIdx.x;
    if (n < N) {
        int d = deg[n];
        dinv[n] = (d > 0) ? rsqrtf((float)d) : 0.0f;
    }
}

__global__ void scan_blocks_kernel(const int* __restrict__ cnt, int* __restrict__ rp,
                                   int* __restrict__ bsum, int N) {
    __shared__ int s[1024];
    int idx = blockIdx.x * 1024 + threadIdx.x;
    int v = (idx < N) ? cnt[idx] : 0;
    s[threadIdx.x] = v;
    __syncthreads();
    for (int off = 1; off < 1024; off <<= 1) {
        int t = (threadIdx.x >= off) ? s[threadIdx.x - off] : 0;
        __syncthreads();
        s[threadIdx.x] += t;
        __syncthreads();
    }
    if (idx < N) rp[idx] = s[threadIdx.x] - v;
    if (threadIdx.x == 1023) bsum[blockIdx.x] = s[1023];
}

__global__ void scan_top_kernel(const int* __restrict__ bsum, int* __restrict__ boff,
                                int nb, int* __restrict__ rp, int N) {
    if (threadIdx.x == 0) {
        int run = 0;
        for (int b = 0; b < nb; ++b) { boff[b] = run; run += bsum[b]; }
        rp[N] = run;
    }
}

__global__ void scan_add_kernel(int* __restrict__ rp, int* __restrict__ cursor,
                                const int* __restrict__ boff, int N) {
    int idx = blockIdx.x * 1024 + threadIdx.x;
    if (idx < N) {
        int r = rp[idx] + boff[blockIdx.x];
        rp[idx] = r;
        cursor[idx] = r;
    }
}

__global__ void scatter_kernel(const int* __restrict__ ei, int E,
                               const float* __restrict__ dinv,
                               int* __restrict__ cursor,
                               int2* __restrict__ epack) {
    int e = blockIdx.x * blockDim.x + threadIdx.x;
    if (e < E) {
        int s = ei[e];
        int d = ei[E + e];
        float nm = -(dinv[s] * dinv[d]);
        int pos = atomicAdd(&cursor[d], 1);
        epack[pos] = make_int2(s, __float_as_int(nm));
    }
}

// ============================================================================
// Layer 1 (scalar features)
// ============================================================================

template <bool USE_PREV>
__global__ void scalar_prop_kernel(const float* __restrict__ tin,
                                   const float* __restrict__ tprev,
                                   float* __restrict__ tout,
                                   const int* __restrict__ rp,
                                   const int2* __restrict__ epack, int N) {
    int n = blockIdx.x * blockDim.x + threadIdx.x;
    if (n >= N) return;
    float acc = 0.0f;
    int e1 = rp[n + 1];
    #pragma unroll 4
    for (int e = rp[n]; e < e1; ++e) {
        int2 md = __ldg(&epack[e]);
        acc += tin[md.x] * __int_as_float(md.y);
    }
    tout[n] = USE_PREV ? (2.0f * acc - tprev[n]) : acc;
}

__global__ void combine1_kernel(const float* __restrict__ x,
                                const float* __restrict__ t1, const float* __restrict__ t2,
                                const float* __restrict__ t3, const float* __restrict__ t4,
                                const float* __restrict__ W1, const float* __restrict__ b1,
                                float* __restrict__ H, int N) {
    int tid = blockIdx.x * blockDim.x + threadIdx.x;
    int n = tid >> 5;
    int l = tid & 31;
    if (n >= N) return;
    float v0 = __ldg(&x[n]),  v1 = __ldg(&t1[n]), v2 = __ldg(&t2[n]);
    float v3 = __ldg(&t3[n]), v4 = __ldg(&t4[n]);
    int j = 2 * l;
    float2 o  = *(const float2*)&b1[j];
    float2 w0 = *(const float2*)&W1[0 * 64 + j];
    float2 w1 = *(const float2*)&W1[1 * 64 + j];
    float2 w2 = *(const float2*)&W1[2 * 64 + j];
    float2 w3 = *(const float2*)&W1[3 * 64 + j];
    float2 w4 = *(const float2*)&W1[4 * 64 + j];
    o.x += v0 * w0.x + v1 * w1.x + v2 * w2.x + v3 * w3.x + v4 * w4.x;
    o.y += v0 * w0.y + v1 * w1.y + v2 * w2.y + v3 * w3.y + v4 * w4.y;
    o.x = fmaxf(o.x, 0.0f);
    o.y = fmaxf(o.y, 0.0f);
    ((float2*)H)[n * 32 + l] = o;
}

// ============================================================================
// Layers 2/3: warp-per-node, half-warp-per-edge float4 kernels
// ============================================================================

// Half-split GEMM accumulate: each half sums rows [32h, 32h+32); combine after.
// tx4 holds cols [4c..4c+4) duplicated across halves. Ws4 = W as float4 rows.
__device__ __forceinline__ float4 gemm_half(const float4 tx4, const float4* Ws4,
                                            int c, int h, float4 o) {
    #pragma unroll
    for (int g = 0; g < 8; ++g) {
        int sl = 8 * h + g;
        float a0 = __shfl_sync(FULLMASK, tx4.x, sl);
        float a1 = __shfl_sync(FULLMASK, tx4.y, sl);
        float a2 = __shfl_sync(FULLMASK, tx4.z, sl);
        float a3 = __shfl_sync(FULLMASK, tx4.w, sl);
        float4 w0 = Ws4[(4 * sl + 0) * 16 + c];
        float4 w1 = Ws4[(4 * sl + 1) * 16 + c];
        float4 w2 = Ws4[(4 * sl + 2) * 16 + c];
        float4 w3 = Ws4[(4 * sl + 3) * 16 + c];
        o.x += a0 * w0.x + a1 * w1.x + a2 * w2.x + a3 * w3.x;
        o.y += a0 * w0.y + a1 * w1.y + a2 * w2.y + a3 * w3.y;
        o.z += a0 * w0.z + a1 * w1.z + a2 * w2.z + a3 * w3.z;
        o.w += a0 * w0.w + a1 * w1.w + a2 * w2.w + a3 * w3.w;
    }
    return o;
}

__device__ __forceinline__ float4 xor_combine(float4 v, int off) {
    v.x += __shfl_xor_sync(FULLMASK, v.x, off);
    v.y += __shfl_xor_sync(FULLMASK, v.y, off);
    v.z += __shfl_xor_sync(FULLMASK, v.z, off);
    v.w += __shfl_xor_sync(FULLMASK, v.w, off);
    return v;
}

// Gather-propagate: acc = sum_e norm*Tin[src], two edges in flight (half-warp each).
__device__ __forceinline__ float4 prop_gather(const float4* __restrict__ Tin4,
                                              const int2* __restrict__ epack,
                                              int e0, int e1, int c, int h) {
    float4 acc = make_float4(0.f, 0.f, 0.f, 0.f);
    #pragma unroll 4
    for (int e = e0 + h; e < e1; e += 2) {
        int2 md = __ldg(&epack[e]);
        float nm = __int_as_float(md.y);
        float4 v = Tin4[(size_t)md.x * 16 + c];
        acc.x += nm * v.x; acc.y += nm * v.y;
        acc.z += nm * v.z; acc.w += nm * v.w;
    }
    return xor_combine(acc, 16);   // both halves now hold the full sum
}

// out = b + H @ W   (layer entry)
__global__ void gemm_bias_kernel(const float* __restrict__ H,
                                 const float* __restrict__ W,
                                 const float* __restrict__ b,
                                 float* __restrict__ out, int N) {
    __shared__ float Ws[4096];
    __shared__ float Bs[64];
    for (int i = threadIdx.x; i < 4096; i += blockDim.x) Ws[i] = W[i];
    if (threadIdx.x < 64) Bs[threadIdx.x] = b[threadIdx.x];
    __syncthreads();
    const float4* Ws4 = (const float4*)Ws;
    int warp = threadIdx.x >> 5, lane = threadIdx.x & 31;
    int c = lane & 15, h = lane >> 4;
    int wpb = blockDim.x >> 5;
    for (int n = blockIdx.x * wpb + warp; n < N; n += gridDim.x * wpb) {
        float4 hv = ((const float4*)H)[n * 16 + c];
        float4 o = (h == 0) ? ((const float4*)Bs)[c] : make_float4(0.f, 0.f, 0.f, 0.f);
        o = gemm_half(hv, Ws4, c, h, o);
        o = xor_combine(o, 16);
        if (h == 0) ((float4*)out)[n * 16 + c] = o;
    }
}

// Tx = 2*prop(Tin) - Tprev (or prop(Tin));  Txout = Tx;  OUT += Tx @ W
template <bool USE_PREV>
__global__ void prop_mid_kernel(const float* __restrict__ Tin,
                                const float* __restrict__ Tprev,
                                float* __restrict__ Txout,
                                float* __restrict__ OUT,
                                const float* __restrict__ W,
                                const int* __restrict__ rp,
                                const int2* __restrict__ epack, int N) {
    __shared__ float Ws[4096];
    for (int i = threadIdx.x; i < 4096; i += blockDim.x) Ws[i] = W[i];
    __syncthreads();
    const float4* Ws4 = (const float4*)Ws;
    const float4* Tin4 = (const float4*)Tin;
    int warp = threadIdx.x >> 5, lane = threadIdx.x & 31;
    int c = lane & 15, h = lane >> 4;
    int wpb = blockDim.x >> 5;
    for (int n = blockIdx.x * wpb + warp; n < N; n += gridDim.x * wpb) {
        int e0 = rp[n], e1 = rp[n + 1];
        float4 acc = prop_gather(Tin4, epack, e0, e1, c, h);
        float4 tx;
        if (USE_PREV) {
            float4 p = ((const float4*)Tprev)[n * 16 + c];
            tx.x = 2.f * acc.x - p.x; tx.y = 2.f * acc.y - p.y;
            tx.z = 2.f * acc.z - p.z; tx.w = 2.f * acc.w - p.w;
        } else tx = acc;
        if (h == 0) ((float4*)Txout)[n * 16 + c] = tx;
        float4 o = (h == 0) ? ((const float4*)OUT)[n * 16 + c]
                            : make_float4(0.f, 0.f, 0.f, 0.f);
        o = gemm_half(tx, Ws4, c, h, o);
        o = xor_combine(o, 16);
        if (h == 0) ((float4*)OUT)[n * 16 + c] = o;
    }
}

// Final prop of a layer, fused with next layer's W[0] GEMM:
//   h = relu(OUT + Tx@W); Hout = h; OUT = bn + h @ Wn
__global__ void prop_last_gemm_kernel(const float* __restrict__ Tin,
                                      const float* __restrict__ Tprev,
                                      float* __restrict__ OUT,
                                      const float* __restrict__ W,
                                      float* __restrict__ Hout,
                                      const float* __restrict__ Wn,
                                      const float* __restrict__ bn,
                                      const int* __restrict__ rp,
                                      const int2* __restrict__ epack, int N) {
    __shared__ float Ws[4096];
    __shared__ float Wns[4096];
    __shared__ float Bs[64];
    for (int i = threadIdx.x; i < 4096; i += blockDim.x) { Ws[i] = W[i]; Wns[i] = Wn[i]; }
    if (threadIdx.x < 64) Bs[threadIdx.x] = bn[threadIdx.x];
    __syncthreads();
    const float4* Ws4 = (const float4*)Ws;
    const float4* Wns4 = (const float4*)Wns;
    const float4* Tin4 = (const float4*)Tin;
    int warp = threadIdx.x >> 5, lane = threadIdx.x & 31;
    int c = lane & 15, h = lane >> 4;
    int wpb = blockDim.x >> 5;
    for (int n = blockIdx.x * wpb + warp; n < N; n += gridDim.x * wpb) {
        int e0 = rp[n], e1 = rp[n + 1];
        float4 acc = prop_gather(Tin4, epack, e0, e1, c, h);
        float4 p = ((const float4*)Tprev)[n * 16 + c];
        float4 tx = make_float4(2.f * acc.x - p.x, 2.f * acc.y - p.y,
                                2.f * acc.z - p.z, 2.f * acc.w - p.w);
        float4 o = (h == 0) ? ((const float4*)OUT)[n * 16 + c]
                            : make_float4(0.f, 0.f, 0.f, 0.f);
        o = gemm_half(tx, Ws4, c, h, o);
        o = xor_combine(o, 16);
        float4 hv = make_float4(fmaxf(o.x, 0.f), fmaxf(o.y, 0.f),
                                fmaxf(o.z, 0.f), fmaxf(o.w, 0.f));
        if (h == 0) ((float4*)Hout)[n * 16 + c] = hv;
        float4 o2 = (h == 0) ? ((const float4*)Bs)[c] : make_float4(0.f, 0.f, 0.f, 0.f);
        o2 = gemm_half(hv, Wns4, c, h, o2);
        o2 = xor_combine(o2, 16);
        if (h == 0) ((float4*)OUT)[n * 16 + c] = o2;
    }
}

// Final prop of layer 3, fused with FC head:
//   h = relu(OUT + Tx@W); out[n] = h . Wfc + bfc
__global__ void prop_last_fc_kernel(const float* __restrict__ Tin,
                                    const float* __restrict__ Tprev,
                                    const float* __restrict__ OUT,
                                    const float* __restrict__ W,
                                    const float* __restrict__ Wfc,
                                    const float* __restrict__ bfc,
                                    float* __restrict__ out,
                                    const int* __restrict__ rp,
                                    const int2* __restrict__ epack, int N) {
    __shared__ float Ws[4096];
    for (int i = threadIdx.x; i < 4096; i += blockDim.x) Ws[i] = W[i];
    __syncthreads();
    const float4* Ws4 = (const float4*)Ws;
    const float4* Tin4 = (const float4*)Tin;
    int warp = threadIdx.x >> 5, lane = threadIdx.x & 31;
    int c = lane & 15, h = lane >> 4;
    int wpb = blockDim.x >> 5;
    float4 wfc = __ldg(&((const float4*)Wfc)[c]);
    float bb = __ldg(bfc);
    for (int n = blockIdx.x * wpb + warp; n < N; n += gridDim.x * wpb) {
        int e0 = rp[n], e1 = rp[n + 1];
        float4 acc = prop_gather(Tin4, epack, e0, e1, c, h);
        float4 p = ((const float4*)Tprev)[n * 16 + c];
        float4 tx = make_float4(2.f * acc.x - p.x, 2.f * acc.y - p.y,
                                2.f * acc.z - p.z, 2.f * acc.w - p.w);
        float4 o = (h == 0) ? ((const float4*)OUT)[n * 16 + c]
                            : make_float4(0.f, 0.f, 0.f, 0.f);
        o = gemm_half(tx, Ws4, c, h, o);
        o = xor_combine(o, 16);
        float pdot = fmaxf(o.x, 0.f) * wfc.x + fmaxf(o.y, 0.f) * wfc.y +
                     fmaxf(o.z, 0.f) * wfc.z + fmaxf(o.w, 0.f) * wfc.w;
        #pragma unroll
        for (int off = 8; off; off >>= 1)
            pdot += __shfl_xor_sync(FULLMASK, pdot, off);
        if (lane == 0) out[n] = pdot + bb;
    }
}

// ============================================================================
// Host launch
// ============================================================================

extern "C" void kernel_launch(void* const* d_in, const int* in_sizes, int n_in,
                              void* d_out, int out_size) {
    const float* x   = (const float*)d_in[0];
    const int*   ei  = (const int*)d_in[1];
    const float* W1  = (const float*)d_in[2];
    const float* b1  = (const float*)d_in[3];
    const float* W2  = (const float*)d_in[4];
    const float* b2  = (const float*)d_in[5];
    const float* W3  = (const float*)d_in[6];
    const float* b3  = (const float*)d_in[7];
    const float* Wfc = (const float*)d_in[8];
    const float* bfc = (const float*)d_in[9];
    float* out = (float*)d_out;

    const int N = in_sizes[0];
    const int E = in_sizes[1] / 2;

    int *deg, *cnt, *rp, *cursor, *bsum, *boff;
    int2* epack;
    float *dinv, *t1, *t2, *t3, *t4, *X0, *X1, *X2, *OUT;
    cudaGetSymbolAddress((void**)&deg,   g_deg);
    cudaGetSymbolAddress((void**)&cnt,   g_cnt);
    cudaGetSymbolAddress((void**)&dinv,  g_dinv);
    cudaGetSymbolAddress((void**)&rp,    g_rp);
    cudaGetSymbolAddress((void**)&cursor,g_cursor);
    cudaGetSymbolAddress((void**)&bsum,  g_bsum);
    cudaGetSymbolAddress((void**)&boff,  g_boff);
    cudaGetSymbolAddress((void**)&epack, g_epack);
    cudaGetSymbolAddress((void**)&t1,    g_t1);
    cudaGetSymbolAddress((void**)&t2,    g_t2);
    cudaGetSymbolAddress((void**)&t3,    g_t3);
    cudaGetSymbolAddress((void**)&t4,    g_t4);
    cudaGetSymbolAddress((void**)&X0,    g_X0);
    cudaGetSymbolAddress((void**)&X1,    g_X1);
    cudaGetSymbolAddress((void**)&X2,    g_X2);
    cudaGetSymbolAddress((void**)&OUT,   g_OUT);

    const int EB = (E + 255) / 256;
    const int NB = (N + 255) / 256;
    const int nb1024 = (N + 1023) / 1024;
    const int PGRID = 1184;

    // --- preprocess: CSR by dst ---
    cudaMemsetAsync(deg, 0, (size_t)N * sizeof(int), 0);
    cudaMemsetAsync(cnt, 0, (size_t)N * sizeof(int), 0);
    deg_hist_kernel<<<EB, 256>>>(ei, E, deg, cnt);
    dinv_kernel<<<NB, 256>>>(deg, dinv, N);
    scan_blocks_kernel<<<nb1024, 1024>>>(cnt, rp, bsum, N);
    scan_top_kernel<<<1, 32>>>(bsum, boff, nb1024, rp, N);
    scan_add_kernel<<<nb1024, 1024>>>(rp, cursor, boff, N);
    scatter_kernel<<<EB, 256>>>(ei, E, dinv, cursor, epack);

    // --- layer 1 (Fin=1) ---
    scalar_prop_kernel<false><<<NB, 256>>>(x,  nullptr, t1, rp, epack, N);
    scalar_prop_kernel<true ><<<NB, 256>>>(t1, x,       t2, rp, epack, N);
    scalar_prop_kernel<true ><<<NB, 256>>>(t2, t1,      t3, rp, epack, N);
    scalar_prop_kernel<true ><<<NB, 256>>>(t3, t2,      t4, rp, epack, N);
    combine1_kernel<<<(N * 32 + 255) / 256, 256>>>(x, t1, t2, t3, t4, W1, b1, X0, N);

    // --- layer 2: T0=X0, T1=X1, T2=X2, T3=X0 ---
    gemm_bias_kernel<<<PGRID, 256>>>(X0, W2, b2, OUT, N);
    prop_mid_kernel<false><<<PGRID, 256>>>(X0, nullptr, X1, OUT, W2 + 1 * 4096, rp, epack, N);
    prop_mid_kernel<true ><<<PGRID, 256>>>(X1, X0,      X2, OUT, W2 + 2 * 4096, rp, epack, N);
    prop_mid_kernel<true ><<<PGRID, 256>>>(X2, X1,      X0, OUT, W2 + 3 * 4096, rp, epack, N);
    // last prop of layer2 + relu + layer3 W[0] GEMM: H3 -> X1, OUT = b3 + H3@W3[0]
    prop_last_gemm_kernel<<<PGRID, 256>>>(X0, X2, OUT, W2 + 4 * 4096,
                                          X1, W3, b3, rp, epack, N);

    // --- layer 3: T0=X1(H3), T1=X2, T2=X0, T3=X1 ---
    prop_mid_kernel<false><<<PGRID, 256>>>(X1, nullptr, X2, OUT, W3 + 1 * 4096, rp, epack, N);
    prop_mid_kernel<true ><<<PGRID, 256>>>(X2, X1,      X0, OUT, W3 + 2 * 4096, rp, epack, N);
    prop_mid_kernel<true ><<<PGRID, 256>>>(X0, X2,      X1, OUT, W3 + 3 * 4096, rp, epack, N);
    // last prop of layer3 + relu + FC head
    prop_last_fc_kernel<<<PGRID, 256>>>(X1, X0, OUT, W3 + 4 * 4096,
                                        Wfc, bfc, out, rp, epack, N);
}

// round 4
// speedup vs baseline: 1.2763x; 1.2175x over previous
#include <cuda_runtime.h>
#include <cuda_bf16.h>

// ============================================================================
// ChebNet R4: pure-gather props + one register-tiled fp32 GEMM per layer.
//   out_layer = [H | Tx1 | Tx2 | Tx3 | Tx4] ([N,320]) @ W_flat ([320,64]) + b
// W[K,Fin,Fout] flattened IS the [320,64] matrix. GEMM: 128x64 block tile,
// full B (80KB) in smem per block, 8x4 register tile per thread -> FFMA-bound.
// ============================================================================

#define FULLMASK 0xffffffffu

static constexpr int NMAX = 131072;
static constexpr int EMAX = 2000000;
static constexpr int NBMAX = 128;

// ---- static device scratch ----
__device__ int   g_deg[NMAX];
__device__ int   g_cnt[NMAX];
__device__ float g_dinv[NMAX];
__device__ int   g_rp[NMAX + 1];
__device__ int   g_cursor[NMAX];
__device__ int   g_bsum[NBMAX];
__device__ int2  g_epack[EMAX];          // (src, norm-as-bits)
__device__ float g_t1[NMAX], g_t2[NMAX], g_t3[NMAX], g_t4[NMAX];
__device__ float g_X0[NMAX * 64];
__device__ float g_X1[NMAX * 64];
__device__ float g_X2[NMAX * 64];
__device__ float g_X3[NMAX * 64];
__device__ float g_X4[NMAX * 64];

// ============================================================================
// Preprocessing (compacted: 5 launches)
// ============================================================================

__global__ void zero2_kernel(int* __restrict__ a, int* __restrict__ b, int N) {
    int i = blockIdx.x * blockDim.x + threadIdx.x;
    if (i < N) { a[i] = 0; b[i] = 0; }
}

__global__ void deg_hist_kernel(const int* __restrict__ ei, int E,
                                int* __restrict__ deg, int* __restrict__ cnt) {
    int e = blockIdx.x * blockDim.x + threadIdx.x;
    if (e < E) {
        atomicAdd(&deg[ei[e]], 1);
        atomicAdd(&cnt[ei[E + e]], 1);
    }
}

// Block scan of cnt (1024/block) + dinv computation fused.
__global__ void scanb_dinv_kernel(const int* __restrict__ cnt,
                                  const int* __restrict__ deg,
                                  int* __restrict__ rp, int* __restrict__ bsum,
                                  float* __restrict__ dinv, int N) {
    __shared__ int s[1024];
    int idx = blockIdx.x * 1024 + threadIdx.x;
    int v = (idx < N) ? cnt[idx] : 0;
    s[threadIdx.x] = v;
    __syncthreads();
    for (int off = 1; off < 1024; off <<= 1) {
        int t = (threadIdx.x >= off) ? s[threadIdx.x - off] : 0;
        __syncthreads();
        s[threadIdx.x] += t;
        __syncthreads();
    }
    if (idx < N) {
        rp[idx] = s[threadIdx.x] - v;   // exclusive within block
        int d = deg[idx];
        dinv[idx] = (d > 0) ? rsqrtf((float)d) : 0.0f;
    }
    if (threadIdx.x == 1023) bsum[blockIdx.x] = s[1023];
}

// Fused top-level scan + offset add.
__global__ void scan_add_kernel(int* __restrict__ rp, int* __restrict__ cursor,
                                const int* __restrict__ bsum, int nb, int N) {
    __shared__ int soff;
    int idx = blockIdx.x * 1024 + threadIdx.x;
    if (threadIdx.x == 0) {
        int r = 0;
        for (int b = 0; b < blockIdx.x; ++b) r += bsum[b];
        soff = r;
        if (blockIdx.x == (unsigned)(gridDim.x - 1)) {
            int tot = r;
            for (int b = blockIdx.x; b < nb; ++b) tot += bsum[b];
            rp[N] = tot;
        }
    }
    __syncthreads();
    if (idx < N) {
        int r = rp[idx] + soff;
        rp[idx] = r;
        cursor[idx] = r;
    }
}

__global__ void scatter_kernel(const int* __restrict__ ei, int E,
                               const float* __restrict__ dinv,
                               int* __restrict__ cursor,
                               int2* __restrict__ epack) {
    int e = blockIdx.x * blockDim.x + threadIdx.x;
    if (e < E) {
        int s = ei[e];
        int d = ei[E + e];
        float nm = -(dinv[s] * dinv[d]);
        int pos = atomicAdd(&cursor[d], 1);
        epack[pos] = make_int2(s, __float_as_int(nm));
    }
}

// ============================================================================
// Layer 1 (scalar features)
// ============================================================================

template <bool USE_PREV>
__global__ void scalar_prop_kernel(const float* __restrict__ tin,
                                   const float* __restrict__ tprev,
                                   float* __restrict__ tout,
                                   const int* __restrict__ rp,
                                   const int2* __restrict__ epack, int N) {
    int n = blockIdx.x * blockDim.x + threadIdx.x;
    if (n >= N) return;
    float acc = 0.0f;
    int e1 = rp[n + 1];
    #pragma unroll 4
    for (int e = rp[n]; e < e1; ++e) {
        int2 md = __ldg(&epack[e]);
        acc += tin[md.x] * __int_as_float(md.y);
    }
    tout[n] = USE_PREV ? (2.0f * acc - tprev[n]) : acc;
}

__global__ void combine1_kernel(const float* __restrict__ x,
                                const float* __restrict__ t1, const float* __restrict__ t2,
                                const float* __restrict__ t3, const float* __restrict__ t4,
                                const float* __restrict__ W1, const float* __restrict__ b1,
                                float* __restrict__ H, int N) {
    int tid = blockIdx.x * blockDim.x + threadIdx.x;
    int n = tid >> 5;
    int l = tid & 31;
    if (n >= N) return;
    float v0 = __ldg(&x[n]),  v1 = __ldg(&t1[n]), v2 = __ldg(&t2[n]);
    float v3 = __ldg(&t3[n]), v4 = __ldg(&t4[n]);
    int j = 2 * l;
    float2 o  = *(const float2*)&b1[j];
    float2 w0 = *(const float2*)&W1[0 * 64 + j];
    float2 w1 = *(const float2*)&W1[1 * 64 + j];
    float2 w2 = *(const float2*)&W1[2 * 64 + j];
    float2 w3 = *(const float2*)&W1[3 * 64 + j];
    float2 w4 = *(const float2*)&W1[4 * 64 + j];
    o.x += v0 * w0.x + v1 * w1.x + v2 * w2.x + v3 * w3.x + v4 * w4.x;
    o.y += v0 * w0.y + v1 * w1.y + v2 * w2.y + v3 * w3.y + v4 * w4.y;
    o.x = fmaxf(o.x, 0.0f);
    o.y = fmaxf(o.y, 0.0f);
    ((float2*)H)[n * 32 + l] = o;
}

// ============================================================================
// Pure gather prop (64-wide): Tx = 2*L^ Tin - Tprev  (or L^ Tin)
// warp-per-node, half-warp-per-edge, float4 per lane.
// ============================================================================

template <bool USE_PREV>
__global__ void prop_kernel(const float* __restrict__ Tin,
                            const float* __restrict__ Tprev,
                            float* __restrict__ Txout,
                            const int* __restrict__ rp,
                            const int2* __restrict__ epack, int N) {
    const float4* Tin4 = (const float4*)Tin;
    int warp = threadIdx.x >> 5, lane = threadIdx.x & 31;
    int c = lane & 15, h = lane >> 4;
    int wpb = blockDim.x >> 5;
    for (int n = blockIdx.x * wpb + warp; n < N; n += gridDim.x * wpb) {
        int e0 = rp[n], e1 = rp[n + 1];
        float4 acc = make_float4(0.f, 0.f, 0.f, 0.f);
        #pragma unroll 4
        for (int e = e0 + h; e < e1; e += 2) {
            int2 md = __ldg(&epack[e]);
            float nm = __int_as_float(md.y);
            float4 v = Tin4[(size_t)md.x * 16 + c];
            acc.x += nm * v.x; acc.y += nm * v.y;
            acc.z += nm * v.z; acc.w += nm * v.w;
        }
        acc.x += __shfl_xor_sync(FULLMASK, acc.x, 16);
        acc.y += __shfl_xor_sync(FULLMASK, acc.y, 16);
        acc.z += __shfl_xor_sync(FULLMASK, acc.z, 16);
        acc.w += __shfl_xor_sync(FULLMASK, acc.w, 16);
        if (h == 0) {
            float4 tx;
            if (USE_PREV) {
                float4 p = ((const float4*)Tprev)[n * 16 + c];
                tx = make_float4(2.f * acc.x - p.x, 2.f * acc.y - p.y,
                                 2.f * acc.z - p.z, 2.f * acc.w - p.w);
            } else tx = acc;
            ((float4*)Txout)[n * 16 + c] = tx;
        }
    }
}

// ============================================================================
// Layer GEMM: out = relu([A0|A1|A2|A3|A4] @ Wflat + b), Wflat = [320,64].
// Block tile 128x64, full B in smem (80KB), A chunk 128x32 staged, 8x4/thread.
// Writes outH in place over A0 (each block touches only its own rows).
// ============================================================================

static constexpr int GEMM_SMEM = (320 * 64 + 128 * 32) * 4;   // 98304 B

__global__ __launch_bounds__(256) void cheb_gemm_kernel(
        const float* __restrict__ A0, const float* __restrict__ A1,
        const float* __restrict__ A2, const float* __restrict__ A3,
        const float* __restrict__ A4,
        const float* __restrict__ Wflat, const float* __restrict__ bias,
        float* outH, int N) {
    extern __shared__ float smem[];
    float*  Bs  = smem;                 // [320][64]
    float*  As  = smem + 320 * 64;      // [128][32]
    float4* Bs4 = (float4*)Bs;
    float4* As4 = (float4*)As;

    // Load full B once per block.
    for (int i = threadIdx.x; i < 5120; i += 256)
        Bs4[i] = ((const float4*)Wflat)[i];

    const int tid = threadIdx.x;
    const int rg = tid >> 4;            // 0..15 row group
    const int cg = tid & 15;            // 0..15 col group (4 cols)
    const int m0 = rg * 8;
    const int blockRow = blockIdx.x * 128;

    const float* bufs[5] = {A0, A1, A2, A3, A4};

    float4 acc[8];
    #pragma unroll
    for (int r = 0; r < 8; ++r) acc[r] = make_float4(0.f, 0.f, 0.f, 0.f);

    const int lm    = tid >> 1;               // row within tile for loads
    const int lcol  = (tid & 1) * 16;         // starting col (of 32-chunk)
    const int grow  = blockRow + lm;

    #pragma unroll
    for (int kc = 0; kc < 10; ++kc) {
        const float* src = bufs[kc >> 1] + ((kc & 1) << 5);
        __syncthreads();
        // Stage A chunk [128][32].
        float4 v0, v1, v2, v3;
        if (grow < N) {
            const float4* s4 = (const float4*)(src + (size_t)grow * 64 + lcol);
            v0 = s4[0]; v1 = s4[1]; v2 = s4[2]; v3 = s4[3];
        } else {
            v0 = v1 = v2 = v3 = make_float4(0.f, 0.f, 0.f, 0.f);
        }
        int ab = lm * 8 + (lcol >> 2);
        As4[ab + 0] = v0; As4[ab + 1] = v1; As4[ab + 2] = v2; As4[ab + 3] = v3;
        __syncthreads();

        #pragma unroll
        for (int k4 = 0; k4 < 8; ++k4) {
            int kb = (kc * 32 + k4 * 4);
            float4 b0 = Bs4[(kb + 0) * 16 + cg];
            float4 b1 = Bs4[(kb + 1) * 16 + cg];
            float4 b2 = Bs4[(kb + 2) * 16 + cg];
            float4 b3 = Bs4[(kb + 3) * 16 + cg];
            #pragma unroll
            for (int r = 0; r < 8; ++r) {
                float4 a = As4[(m0 + r) * 8 + k4];
                acc[r].x += a.x * b0.x + a.y * b1.x + a.z * b2.x + a.w * b3.x;
                acc[r].y += a.x * b0.y + a.y * b1.y + a.z * b2.y + a.w * b3.y;
                acc[r].z += a.x * b0.z + a.y * b1.z + a.z * b2.z + a.w * b3.z;
                acc[r].w += a.x * b0.w + a.y * b1.w + a.z * b2.w + a.w * b3.w;
            }
        }
    }

    float4 bv = *(const float4*)&bias[cg * 4];
    #pragma unroll
    for (int r = 0; r < 8; ++r) {
        int row = blockRow + m0 + r;
        if (row < N) {
            float4 o = make_float4(fmaxf(acc[r].x + bv.x, 0.f),
                                   fmaxf(acc[r].y + bv.y, 0.f),
                                   fmaxf(acc[r].z + bv.z, 0.f),
                                   fmaxf(acc[r].w + bv.w, 0.f));
            ((float4*)outH)[(size_t)row * 16 + cg] = o;
        }
    }
}

// ============================================================================
// FC head
// ============================================================================

__global__ void fc_kernel(const float* __restrict__ H,
                          const float* __restrict__ Wfc,
                          const float* __restrict__ bfc,
                          float* __restrict__ out, int N) {
    int warp = threadIdx.x >> 5, lane = threadIdx.x & 31;
    int wpb = blockDim.x >> 5;
    float2 w = ((const float2*)Wfc)[lane];
    float bb = __ldg(bfc);
    for (int n = blockIdx.x * wpb + warp; n < N; n += gridDim.x * wpb) {
        float2 h = ((const float2*)H)[n * 32 + lane];
        float p = h.x * w.x + h.y * w.y;
        #pragma unroll
        for (int off = 16; off; off >>= 1)
            p += __shfl_xor_sync(FULLMASK, p, off);
        if (lane == 0) out[n] = p + bb;
    }
}

// ============================================================================
// Host launch
// ============================================================================

extern "C" void kernel_launch(void* const* d_in, const int* in_sizes, int n_in,
                              void* d_out, int out_size) {
    const float* x   = (const float*)d_in[0];
    const int*   ei  = (const int*)d_in[1];
    const float* W1  = (const float*)d_in[2];
    const float* b1  = (const float*)d_in[3];
    const float* W2  = (const float*)d_in[4];
    const float* b2  = (const float*)d_in[5];
    const float* W3  = (const float*)d_in[6];
    const float* b3  = (const float*)d_in[7];
    const float* Wfc = (const float*)d_in[8];
    const float* bfc = (const float*)d_in[9];
    float* out = (float*)d_out;

    const int N = in_sizes[0];
    const int E = in_sizes[1] / 2;

    int *deg, *cnt, *rp, *cursor, *bsum;
    int2* epack;
    float *dinv, *t1, *t2, *t3, *t4, *X0, *X1, *X2, *X3, *X4;
    cudaGetSymbolAddress((void**)&deg,   g_deg);
    cudaGetSymbolAddress((void**)&cnt,   g_cnt);
    cudaGetSymbolAddress((void**)&dinv,  g_dinv);
    cudaGetSymbolAddress((void**)&rp,    g_rp);
    cudaGetSymbolAddress((void**)&cursor,g_cursor);
    cudaGetSymbolAddress((void**)&bsum,  g_bsum);
    cudaGetSymbolAddress((void**)&epack, g_epack);
    cudaGetSymbolAddress((void**)&t1,    g_t1);
    cudaGetSymbolAddress((void**)&t2,    g_t2);
    cudaGetSymbolAddress((void**)&t3,    g_t3);
    cudaGetSymbolAddress((void**)&t4,    g_t4);
    cudaGetSymbolAddress((void**)&X0,    g_X0);
    cudaGetSymbolAddress((void**)&X1,    g_X1);
    cudaGetSymbolAddress((void**)&X2,    g_X2);
    cudaGetSymbolAddress((void**)&X3,    g_X3);
    cudaGetSymbolAddress((void**)&X4,    g_X4);

    static bool attr_done = false;
    if (!attr_done) {
        cudaFuncSetAttribute(cheb_gemm_kernel,
                             cudaFuncAttributeMaxDynamicSharedMemorySize, GEMM_SMEM);
        attr_done = true;
    }

    const int EB = (E + 255) / 256;
    const int NB = (N + 255) / 256;
    const int nb1024 = (N + 1023) / 1024;
    const int PGRID = 1184;
    const int GB = (N + 127) / 128;

    // --- preprocess: CSR by dst (5 launches) ---
    zero2_kernel<<<NB, 256>>>(deg, cnt, N);
    deg_hist_kernel<<<EB, 256>>>(ei, E, deg, cnt);
    scanb_dinv_kernel<<<nb1024, 1024>>>(cnt, deg, rp, bsum, dinv, N);
    scan_add_kernel<<<nb1024, 1024>>>(rp, cursor, bsum, nb1024, N);
    scatter_kernel<<<EB, 256>>>(ei, E, dinv, cursor, epack);

    // --- layer 1 (Fin=1) -> H2 in X0 ---
    scalar_prop_kernel<false><<<NB, 256>>>(x,  nullptr, t1, rp, epack, N);
    scalar_prop_kernel<true ><<<NB, 256>>>(t1, x,       t2, rp, epack, N);
    scalar_prop_kernel<true ><<<NB, 256>>>(t2, t1,      t3, rp, epack, N);
    scalar_prop_kernel<true ><<<NB, 256>>>(t3, t2,      t4, rp, epack, N);
    combine1_kernel<<<(N * 32 + 255) / 256, 256>>>(x, t1, t2, t3, t4, W1, b1, X0, N);

    // --- layer 2: H=X0; props -> X1..X4; GEMM -> X0 (in place) ---
    prop_kernel<false><<<PGRID, 256>>>(X0, nullptr, X1, rp, epack, N);
    prop_kernel<true ><<<PGRID, 256>>>(X1, X0,      X2, rp, epack, N);
    prop_kernel<true ><<<PGRID, 256>>>(X2, X1,      X3, rp, epack, N);
    prop_kernel<true ><<<PGRID, 256>>>(X3, X2,      X4, rp, epack, N);
    cheb_gemm_kernel<<<GB, 256, GEMM_SMEM>>>(X0, X1, X2, X3, X4, W2, b2, X0, N);

    // --- layer 3: H=X0; props -> X1..X4; GEMM -> X0 (in place) ---
    prop_kernel<false><<<PGRID, 256>>>(X0, nullptr, X1, rp, epack, N);
    prop_kernel<true ><<<PGRID, 256>>>(X1, X0,      X2, rp, epack, N);
    prop_kernel<true ><<<PGRID, 256>>>(X2, X1,      X3, rp, epack, N);
    prop_kernel<true ><<<PGRID, 256>>>(X3, X2,      X4, rp, epack, N);
    cheb_gemm_kernel<<<GB, 256, GEMM_SMEM>>>(X0, X1, X2, X3, X4, W3, b3, X0, N);

    // --- FC head ---
    fc_kernel<<<PGRID, 256>>>(X0, Wfc, bfc, out, N);
}

// round 5
// speedup vs baseline: 1.5452x; 1.2107x over previous
#include <cuda_runtime.h>
#include <cuda_bf16.h>

// ============================================================================
// ChebNet R5: monomial-basis props (pure L̂ powers, weights pre-transformed) +
// f32x2 packed-FMA GEMM.
//   out = [H|P1|P2|P3|P4] @ W'flat + b,  P_j = L̂^j H
// ============================================================================

#define FULLMASK 0xffffffffu

static constexpr int NMAX = 131072;
static constexpr int EMAX = 2000000;
static constexpr int NBMAX = 128;

// ---- static device scratch ----
__device__ int   g_deg[NMAX];
__device__ int   g_cnt[NMAX];
__device__ float g_dinv[NMAX];
__device__ int   g_rp[NMAX + 1];
__device__ int   g_cursor[NMAX];
__device__ int   g_bsum[NBMAX];
__device__ int2  g_epack[EMAX];
__device__ float g_t1[NMAX], g_t2[NMAX], g_t3[NMAX], g_t4[NMAX];
__device__ float g_X0[NMAX * 64];
__device__ float g_X1[NMAX * 64];
__device__ float g_X2[NMAX * 64];
__device__ float g_X3[NMAX * 64];
__device__ float g_X4[NMAX * 64];
__device__ float g_W1t[5 * 64];
__device__ float g_W2t[5 * 64 * 64];
__device__ float g_W3t[5 * 64 * 64];

// ---- f32x2 packed FMA helpers ----
__device__ __forceinline__ unsigned long long pk2(float x, float y) {
    unsigned long long r;
    asm("mov.b64 %0, {%1, %2};" : "=l"(r) : "f"(x), "f"(y));
    return r;
}
__device__ __forceinline__ void fma2(unsigned long long& d,
                                     unsigned long long a, unsigned long long b) {
    asm("fma.rn.f32x2 %0, %1, %2, %0;" : "+l"(d) : "l"(a), "l"(b));
}
__device__ __forceinline__ float2 upk2(unsigned long long v) {
    float2 f;
    asm("mov.b64 {%0, %1}, %2;" : "=f"(f.x), "=f"(f.y) : "l"(v));
    return f;
}

// ============================================================================
// Weight basis transform:  W'0=W0-W2+W4, W'1=W1-3W3, W'2=2W2-8W4, W'3=4W3, W'4=8W4
// ============================================================================

__global__ void wtrans_kernel(const float* __restrict__ W1, const float* __restrict__ W2,
                              const float* __restrict__ W3,
                              float* __restrict__ W1t, float* __restrict__ W2t,
                              float* __restrict__ W3t) {
    int i = blockIdx.x * blockDim.x + threadIdx.x;
    const float* W; float* Wt; int F, m;
    if (i < 64)            { W = W1; Wt = W1t; F = 64;   m = i; }
    else if (i < 64 + 4096){ W = W2; Wt = W2t; F = 4096; m = i - 64; }
    else if (i < 64 + 8192){ W = W3; Wt = W3t; F = 4096; m = i - 4160; }
    else return;
    float w0 = W[m], w1 = W[F + m], w2 = W[2 * F + m], w3 = W[3 * F + m], w4 = W[4 * F + m];
    Wt[m]         = w0 - w2 + w4;
    Wt[F + m]     = w1 - 3.f * w3;
    Wt[2 * F + m] = 2.f * w2 - 8.f * w4;
    Wt[3 * F + m] = 4.f * w3;
    Wt[4 * F + m] = 8.f * w4;
}

// ============================================================================
// Preprocessing
// ============================================================================

__global__ void zero2_kernel(int* __restrict__ a, int* __restrict__ b, int N) {
    int i = blockIdx.x * blockDim.x + threadIdx.x;
    if (i < N) { a[i] = 0; b[i] = 0; }
}

__global__ void deg_hist_kernel(const int* __restrict__ ei, int E,
                                int* __restrict__ deg, int* __restrict__ cnt) {
    int e = blockIdx.x * blockDim.x + threadIdx.x;
    if (e < E) {
        atomicAdd(&deg[ei[e]], 1);
        atomicAdd(&cnt[ei[E + e]], 1);
    }
}

__global__ void scanb_dinv_kernel(const int* __restrict__ cnt,
                                  const int* __restrict__ deg,
                                  int* __restrict__ rp, int* __restrict__ bsum,
                                  float* __restrict__ dinv, int N) {
    __shared__ int s[1024];
    int idx = blockIdx.x * 1024 + threadIdx.x;
    int v = (idx < N) ? cnt[idx] : 0;
    s[threadIdx.x] = v;
    __syncthreads();
    for (int off = 1; off < 1024; off <<= 1) {
        int t = (threadIdx.x >= off) ? s[threadIdx.x - off] : 0;
        __syncthreads();
        s[threadIdx.x] += t;
        __syncthreads();
    }
    if (idx < N) {
        rp[idx] = s[threadIdx.x] - v;
        int d = deg[idx];
        dinv[idx] = (d > 0) ? rsqrtf((float)d) : 0.0f;
    }
    if (threadIdx.x == 1023) bsum[blockIdx.x] = s[1023];
}

// Parallel top-scan (redundant per block) + offset add.
__global__ void scan_add_kernel(int* __restrict__ rp, int* __restrict__ cursor,
                                const int* __restrict__ bsum, int nb, int N) {
    __shared__ int sb[NBMAX];
    int idx = blockIdx.x * 1024 + threadIdx.x;
    if (threadIdx.x < NBMAX)
        sb[threadIdx.x] = (threadIdx.x < nb) ? bsum[threadIdx.x] : 0;
    __syncthreads();
    for (int off = 1; off < NBMAX; off <<= 1) {
        int t = (threadIdx.x < NBMAX && threadIdx.x >= off) ? sb[threadIdx.x - off] : 0;
        __syncthreads();
        if (threadIdx.x < NBMAX) sb[threadIdx.x] += t;
        __syncthreads();
    }
    int soff = (blockIdx.x == 0) ? 0 : sb[blockIdx.x - 1];
    if (blockIdx.x == (unsigned)(gridDim.x - 1) && threadIdx.x == 0)
        rp[N] = sb[nb - 1];
    if (idx < N) {
        int r = rp[idx] + soff;
        rp[idx] = r;
        cursor[idx] = r;
    }
}

__global__ void scatter_kernel(const int* __restrict__ ei, int E,
                               const float* __restrict__ dinv,
                               int* __restrict__ cursor,
                               int2* __restrict__ epack) {
    int e = blockIdx.x * blockDim.x + threadIdx.x;
    if (e < E) {
        int s = ei[e];
        int d = ei[E + e];
        float nm = -(dinv[s] * dinv[d]);
        int pos = atomicAdd(&cursor[d], 1);
        epack[pos] = make_int2(s, __float_as_int(nm));
    }
}

// ============================================================================
// Layer 1 (scalar features): pure powers p_k = L̂ p_{k-1}
// ============================================================================

__global__ void scalar_prop_kernel(const float* __restrict__ tin,
                                   float* __restrict__ tout,
                                   const int* __restrict__ rp,
                                   const int2* __restrict__ epack, int N) {
    int n = blockIdx.x * blockDim.x + threadIdx.x;
    if (n >= N) return;
    float acc = 0.0f;
    int e1 = rp[n + 1];
    #pragma unroll 4
    for (int e = rp[n]; e < e1; ++e) {
        int2 md = __ldg(&epack[e]);
        acc += tin[md.x] * __int_as_float(md.y);
    }
    tout[n] = acc;
}

__global__ void combine1_kernel(const float* __restrict__ x,
                                const float* __restrict__ t1, const float* __restrict__ t2,
                                const float* __restrict__ t3, const float* __restrict__ t4,
                                const float* __restrict__ W1t, const float* __restrict__ b1,
                                float* __restrict__ H, int N) {
    int tid = blockIdx.x * blockDim.x + threadIdx.x;
    int n = tid >> 5;
    int l = tid & 31;
    if (n >= N) return;
    float v0 = __ldg(&x[n]),  v1 = __ldg(&t1[n]), v2 = __ldg(&t2[n]);
    float v3 = __ldg(&t3[n]), v4 = __ldg(&t4[n]);
    int j = 2 * l;
    float2 o  = *(const float2*)&b1[j];
    float2 w0 = *(const float2*)&W1t[0 * 64 + j];
    float2 w1 = *(const float2*)&W1t[1 * 64 + j];
    float2 w2 = *(const float2*)&W1t[2 * 64 + j];
    float2 w3 = *(const float2*)&W1t[3 * 64 + j];
    float2 w4 = *(const float2*)&W1t[4 * 64 + j];
    o.x += v0 * w0.x + v1 * w1.x + v2 * w2.x + v3 * w3.x + v4 * w4.x;
    o.y += v0 * w0.y + v1 * w1.y + v2 * w2.y + v3 * w3.y + v4 * w4.y;
    o.x = fmaxf(o.x, 0.0f);
    o.y = fmaxf(o.y, 0.0f);
    ((float2*)H)[n * 32 + l] = o;
}

// ============================================================================
// Pure gather prop: P = L̂ Tin.  Warp-per-node, half-warp-per-edge, float4.
// ============================================================================

__global__ void prop_kernel(const float* __restrict__ Tin,
                            float* __restrict__ Pout,
                            const int* __restrict__ rp,
                            const int2* __restrict__ epack, int N) {
    const float4* Tin4 = (const float4*)Tin;
    int warp = threadIdx.x >> 5, lane = threadIdx.x & 31;
    int c = lane & 15, h = lane >> 4;
    int wpb = blockDim.x >> 5;
    for (int n = blockIdx.x * wpb + warp; n < N; n += gridDim.x * wpb) {
        int e0 = rp[n], e1 = rp[n + 1];
        float4 acc = make_float4(0.f, 0.f, 0.f, 0.f);
        #pragma unroll 4
        for (int e = e0 + h; e < e1; e += 2) {
            int2 md = __ldg(&epack[e]);
            float nm = __int_as_float(md.y);
            float4 v = Tin4[(size_t)md.x * 16 + c];
            acc.x += nm * v.x; acc.y += nm * v.y;
            acc.z += nm * v.z; acc.w += nm * v.w;
        }
        acc.x += __shfl_xor_sync(FULLMASK, acc.x, 16);
        acc.y += __shfl_xor_sync(FULLMASK, acc.y, 16);
        acc.z += __shfl_xor_sync(FULLMASK, acc.z, 16);
        acc.w += __shfl_xor_sync(FULLMASK, acc.w, 16);
        if (h == 0) ((float4*)Pout)[n * 16 + c] = acc;
    }
}

// ============================================================================
// Layer GEMM (f32x2): out = relu([A0..A4] @ Wflat + b), Wflat [320,64].
// 128x64 block tile, full B in smem, 8 rows x 4 cols per thread.
// ============================================================================

static constexpr int GEMM_SMEM = (320 * 64 + 128 * 32) * 4;   // 98304 B

__global__ __launch_bounds__(256) void cheb_gemm_kernel(
        const float* __restrict__ A0, const float* __restrict__ A1,
        const float* __restrict__ A2, const float* __restrict__ A3,
        const float* __restrict__ A4,
        const float* __restrict__ Wflat, const float* __restrict__ bias,
        float* outH, int N) {
    extern __shared__ float smem[];
    float*  Bs  = smem;                 // [320][64]
    float*  As  = smem + 320 * 64;      // [128][32]
    float4* Bs4 = (float4*)Bs;
    const ulonglong2* Bs2 = (const ulonglong2*)Bs;
    float4* As4 = (float4*)As;

    for (int i = threadIdx.x; i < 5120; i += 256)
        Bs4[i] = ((const float4*)Wflat)[i];

    const int tid = threadIdx.x;
    const int rg = tid >> 4;
    const int cg = tid & 15;
    const int m0 = rg * 8;
    const int blockRow = blockIdx.x * 128;

    const float* bufs[5] = {A0, A1, A2, A3, A4};

    unsigned long long accL[8], accH[8];
    #pragma unroll
    for (int r = 0; r < 8; ++r) { accL[r] = 0ull; accH[r] = 0ull; }

    const int lm   = tid >> 1;
    const int lcol = (tid & 1) * 16;
    const int grow = blockRow + lm;

    #pragma unroll
    for (int kc = 0; kc < 10; ++kc) {
        const float* src = bufs[kc >> 1] + ((kc & 1) << 5);
        __syncthreads();
        float4 v0, v1, v2, v3;
        if (grow < N) {
            const float4* s4 = (const float4*)(src + (size_t)grow * 64 + lcol);
            v0 = s4[0]; v1 = s4[1]; v2 = s4[2]; v3 = s4[3];
        } else {
            v0 = v1 = v2 = v3 = make_float4(0.f, 0.f, 0.f, 0.f);
        }
        int ab = lm * 8 + (lcol >> 2);
        As4[ab + 0] = v0; As4[ab + 1] = v1; As4[ab + 2] = v2; As4[ab + 3] = v3;
        __syncthreads();

        #pragma unroll
        for (int k4 = 0; k4 < 8; ++k4) {
            int kb = (kc * 32 + k4 * 4);
            ulonglong2 b0 = Bs2[(kb + 0) * 16 + cg];
            ulonglong2 b1 = Bs2[(kb + 1) * 16 + cg];
            ulonglong2 b2 = Bs2[(kb + 2) * 16 + cg];
            ulonglong2 b3 = Bs2[(kb + 3) * 16 + cg];
            #pragma unroll
            for (int r = 0; r < 8; ++r) {
                float4 a = As4[(m0 + r) * 8 + k4];
                unsigned long long ax = pk2(a.x, a.x);
                unsigned long long ay = pk2(a.y, a.y);
                unsigned long long az = pk2(a.z, a.z);
                unsigned long long aw = pk2(a.w, a.w);
                fma2(accL[r], ax, b0.x); fma2(accH[r], ax, b0.y);
                fma2(accL[r], ay, b1.x); fma2(accH[r], ay, b1.y);
                fma2(accL[r], az, b2.x); fma2(accH[r], az, b2.y);
                fma2(accL[r], aw, b3.x); fma2(accH[r], aw, b3.y);
            }
        }
    }

    float4 bv = *(const float4*)&bias[cg * 4];
    #pragma unroll
    for (int r = 0; r < 8; ++r) {
        int row = blockRow + m0 + r;
        if (row < N) {
            float2 lo = upk2(accL[r]);
            float2 hi = upk2(accH[r]);
            float4 o = make_float4(fmaxf(lo.x + bv.x, 0.f),
                                   fmaxf(lo.y + bv.y, 0.f),
                                   fmaxf(hi.x + bv.z, 0.f),
                                   fmaxf(hi.y + bv.w, 0.f));
            ((float4*)outH)[(size_t)row * 16 + cg] = o;
        }
    }
}

// ============================================================================
// FC head
// ============================================================================

__global__ void fc_kernel(const float* __restrict__ H,
                          const float* __restrict__ Wfc,
                          const float* __restrict__ bfc,
                          float* __restrict__ out, int N) {
    int warp = threadIdx.x >> 5, lane = threadIdx.x & 31;
    int wpb = blockDim.x >> 5;
    float2 w = ((const float2*)Wfc)[lane];
    float bb = __ldg(bfc);
    for (int n = blockIdx.x * wpb + warp; n < N; n += gridDim.x * wpb) {
        float2 h = ((const float2*)H)[n * 32 + lane];
        float p = h.x * w.x + h.y * w.y;
        #pragma unroll
        for (int off = 16; off; off >>= 1)
            p += __shfl_xor_sync(FULLMASK, p, off);
        if (lane == 0) out[n] = p + bb;
    }
}

// ============================================================================
// Host launch
// ============================================================================

extern "C" void kernel_launch(void* const* d_in, const int* in_sizes, int n_in,
                              void* d_out, int out_size) {
    const float* x   = (const float*)d_in[0];
    const int*   ei  = (const int*)d_in[1];
    const float* W1  = (const float*)d_in[2];
    const float* b1  = (const float*)d_in[3];
    const float* W2  = (const float*)d_in[4];
    const float* b2  = (const float*)d_in[5];
    const float* W3  = (const float*)d_in[6];
    const float* b3  = (const float*)d_in[7];
    const float* Wfc = (const float*)d_in[8];
    const float* bfc = (const float*)d_in[9];
    float* out = (float*)d_out;

    const int N = in_sizes[0];
    const int E = in_sizes[1] / 2;

    int *deg, *cnt, *rp, *cursor, *bsum;
    int2* epack;
    float *dinv, *t1, *t2, *t3, *t4, *X0, *X1, *X2, *X3, *X4, *W1t, *W2t, *W3t;
    cudaGetSymbolAddress((void**)&deg,   g_deg);
    cudaGetSymbolAddress((void**)&cnt,   g_cnt);
    cudaGetSymbolAddress((void**)&dinv,  g_dinv);
    cudaGetSymbolAddress((void**)&rp,    g_rp);
    cudaGetSymbolAddress((void**)&cursor,g_cursor);
    cudaGetSymbolAddress((void**)&bsum,  g_bsum);
    cudaGetSymbolAddress((void**)&epack, g_epack);
    cudaGetSymbolAddress((void**)&t1,    g_t1);
    cudaGetSymbolAddress((void**)&t2,    g_t2);
    cudaGetSymbolAddress((void**)&t3,    g_t3);
    cudaGetSymbolAddress((void**)&t4,    g_t4);
    cudaGetSymbolAddress((void**)&X0,    g_X0);
    cudaGetSymbolAddress((void**)&X1,    g_X1);
    cudaGetSymbolAddress((void**)&X2,    g_X2);
    cudaGetSymbolAddress((void**)&X3,    g_X3);
    cudaGetSymbolAddress((void**)&X4,    g_X4);
    cudaGetSymbolAddress((void**)&W1t,   g_W1t);
    cudaGetSymbolAddress((void**)&W2t,   g_W2t);
    cudaGetSymbolAddress((void**)&W3t,   g_W3t);

    static bool attr_done = false;
    if (!attr_done) {
        cudaFuncSetAttribute(cheb_gemm_kernel,
                             cudaFuncAttributeMaxDynamicSharedMemorySize, GEMM_SMEM);
        attr_done = true;
    }

    const int EB = (E + 255) / 256;
    const int NB = (N + 255) / 256;
    const int nb1024 = (N + 1023) / 1024;
    const int PGRID = 1184;
    const int GB = (N + 127) / 128;

    // --- weight transform + preprocess ---
    wtrans_kernel<<<(64 + 8192 + 255) / 256, 256>>>(W1, W2, W3, W1t, W2t, W3t);
    zero2_kernel<<<NB, 256>>>(deg, cnt, N);
    deg_hist_kernel<<<EB, 256>>>(ei, E, deg, cnt);
    scanb_dinv_kernel<<<nb1024, 1024>>>(cnt, deg, rp, bsum, dinv, N);
    scan_add_kernel<<<nb1024, 1024>>>(rp, cursor, bsum, nb1024, N);
    scatter_kernel<<<EB, 256>>>(ei, E, dinv, cursor, epack);

    // --- layer 1 (Fin=1): pure powers ---
    scalar_prop_kernel<<<NB, 256>>>(x,  t1, rp, epack, N);
    scalar_prop_kernel<<<NB, 256>>>(t1, t2, rp, epack, N);
    scalar_prop_kernel<<<NB, 256>>>(t2, t3, rp, epack, N);
    scalar_prop_kernel<<<NB, 256>>>(t3, t4, rp, epack, N);
    combine1_kernel<<<(N * 32 + 255) / 256, 256>>>(x, t1, t2, t3, t4, W1t, b1, X0, N);

    // --- layer 2: H=X0; P1..P4 -> X1..X4; GEMM -> X0 ---
    prop_kernel<<<PGRID, 256>>>(X0, X1, rp, epack, N);
    prop_kernel<<<PGRID, 256>>>(X1, X2, rp, epack, N);
    prop_kernel<<<PGRID, 256>>>(X2, X3, rp, epack, N);
    prop_kernel<<<PGRID, 256>>>(X3, X4, rp, epack, N);
    cheb_gemm_kernel<<<GB, 256, GEMM_SMEM>>>(X0, X1, X2, X3, X4, W2t, b2, X0, N);

    // --- layer 3 ---
    prop_kernel<<<PGRID, 256>>>(X0, X1, rp, epack, N);
    prop_kernel<<<PGRID, 256>>>(X1, X2, rp, epack, N);
    prop_kernel<<<PGRID, 256>>>(X2, X3, rp, epack, N);
    prop_kernel<<<PGRID, 256>>>(X3, X4, rp, epack, N);
    cheb_gemm_kernel<<<GB, 256, GEMM_SMEM>>>(X0, X1, X2, X3, X4, W3t, b3, X0, N);

    // --- FC head ---
    fc_kernel<<<PGRID, 256>>>(X0, Wfc, bfc, out, N);
}

// round 6
// speedup vs baseline: 1.5978x; 1.0340x over previous
#include <cuda_runtime.h>
#include <cuda_bf16.h>

// ============================================================================
// ChebNet R6: monomial props + split GEMM with stream overlap + fused FC.
//   partial(s1) = b + X0..X3 @ W'0..3   (overlaps prop4 on main stream)
//   final(main) = relu(OUT + X4 @ W'4)  [layer3: fused FC head]
// ============================================================================

#define FULLMASK 0xffffffffu

static constexpr int NMAX = 131072;
static constexpr int EMAX = 2000000;
static constexpr int NBMAX = 128;

// ---- static device scratch ----
__device__ int   g_deg[NMAX];
__device__ int   g_cnt[NMAX];
__device__ float g_dinv[NMAX];
__device__ int   g_rp[NMAX + 1];
__device__ int   g_cursor[NMAX];
__device__ int   g_bsum[NBMAX];
__device__ int2  g_epack[EMAX];
__device__ float g_t1[NMAX], g_t2[NMAX], g_t3[NMAX], g_t4[NMAX];
__device__ float g_X0[NMAX * 64];
__device__ float g_X1[NMAX * 64];
__device__ float g_X2[NMAX * 64];
__device__ float g_X3[NMAX * 64];
__device__ float g_X4[NMAX * 64];
__device__ float g_OUT[NMAX * 64];
__device__ float g_W1t[5 * 64];
__device__ float g_W2t[5 * 64 * 64];
__device__ float g_W3t[5 * 64 * 64];

// ---- f32x2 packed FMA helpers ----
__device__ __forceinline__ unsigned long long pk2(float x, float y) {
    unsigned long long r;
    asm("mov.b64 %0, {%1, %2};" : "=l"(r) : "f"(x), "f"(y));
    return r;
}
__device__ __forceinline__ void fma2(unsigned long long& d,
                                     unsigned long long a, unsigned long long b) {
    asm("fma.rn.f32x2 %0, %1, %2, %0;" : "+l"(d) : "l"(a), "l"(b));
}
__device__ __forceinline__ float2 upk2(unsigned long long v) {
    float2 f;
    asm("mov.b64 {%0, %1}, %2;" : "=f"(f.x), "=f"(f.y) : "l"(v));
    return f;
}

// ============================================================================
// Weight basis transform
// ============================================================================

__global__ void wtrans_kernel(const float* __restrict__ W1, const float* __restrict__ W2,
                              const float* __restrict__ W3,
                              float* __restrict__ W1t, float* __restrict__ W2t,
                              float* __restrict__ W3t) {
    int i = blockIdx.x * blockDim.x + threadIdx.x;
    const float* W; float* Wt; int F, m;
    if (i < 64)            { W = W1; Wt = W1t; F = 64;   m = i; }
    else if (i < 64 + 4096){ W = W2; Wt = W2t; F = 4096; m = i - 64; }
    else if (i < 64 + 8192){ W = W3; Wt = W3t; F = 4096; m = i - 4160; }
    else return;
    float w0 = W[m], w1 = W[F + m], w2 = W[2 * F + m], w3 = W[3 * F + m], w4 = W[4 * F + m];
    Wt[m]         = w0 - w2 + w4;
    Wt[F + m]     = w1 - 3.f * w3;
    Wt[2 * F + m] = 2.f * w2 - 8.f * w4;
    Wt[3 * F + m] = 4.f * w3;
    Wt[4 * F + m] = 8.f * w4;
}

// ============================================================================
// Preprocessing
// ============================================================================

__global__ void zero2_kernel(int* __restrict__ a, int* __restrict__ b, int N) {
    int i = blockIdx.x * blockDim.x + threadIdx.x;
    if (i < N) { a[i] = 0; b[i] = 0; }
}

__global__ void deg_hist_kernel(const int* __restrict__ ei, int E,
                                int* __restrict__ deg, int* __restrict__ cnt) {
    int e = blockIdx.x * blockDim.x + threadIdx.x;
    if (e < E) {
        atomicAdd(&deg[ei[e]], 1);
        atomicAdd(&cnt[ei[E + e]], 1);
    }
}

__global__ void scanb_dinv_kernel(const int* __restrict__ cnt,
                                  const int* __restrict__ deg,
                                  int* __restrict__ rp, int* __restrict__ bsum,
                                  float* __restrict__ dinv, int N) {
    __shared__ int s[1024];
    int idx = blockIdx.x * 1024 + threadIdx.x;
    int v = (idx < N) ? cnt[idx] : 0;
    s[threadIdx.x] = v;
    __syncthreads();
    for (int off = 1; off < 1024; off <<= 1) {
        int t = (threadIdx.x >= off) ? s[threadIdx.x - off] : 0;
        __syncthreads();
        s[threadIdx.x] += t;
        __syncthreads();
    }
    if (idx < N) {
        rp[idx] = s[threadIdx.x] - v;
        int d = deg[idx];
        dinv[idx] = (d > 0) ? rsqrtf((float)d) : 0.0f;
    }
    if (threadIdx.x == 1023) bsum[blockIdx.x] = s[1023];
}

__global__ void scan_add_kernel(int* __restrict__ rp, int* __restrict__ cursor,
                                const int* __restrict__ bsum, int nb, int N) {
    __shared__ int sb[NBMAX];
    int idx = blockIdx.x * 1024 + threadIdx.x;
    if (threadIdx.x < NBMAX)
        sb[threadIdx.x] = (threadIdx.x < nb) ? bsum[threadIdx.x] : 0;
    __syncthreads();
    for (int off = 1; off < NBMAX; off <<= 1) {
        int t = (threadIdx.x < NBMAX && threadIdx.x >= off) ? sb[threadIdx.x - off] : 0;
        __syncthreads();
        if (threadIdx.x < NBMAX) sb[threadIdx.x] += t;
        __syncthreads();
    }
    int soff = (blockIdx.x == 0) ? 0 : sb[blockIdx.x - 1];
    if (blockIdx.x == (unsigned)(gridDim.x - 1) && threadIdx.x == 0)
        rp[N] = sb[nb - 1];
    if (idx < N) {
        int r = rp[idx] + soff;
        rp[idx] = r;
        cursor[idx] = r;
    }
}

__global__ void scatter_kernel(const int* __restrict__ ei, int E,
                               const float* __restrict__ dinv,
                               int* __restrict__ cursor,
                               int2* __restrict__ epack) {
    int e = blockIdx.x * blockDim.x + threadIdx.x;
    if (e < E) {
        int s = ei[e];
        int d = ei[E + e];
        float nm = -(dinv[s] * dinv[d]);
        int pos = atomicAdd(&cursor[d], 1);
        epack[pos] = make_int2(s, __float_as_int(nm));
    }
}

// ============================================================================
// Layer 1 (scalar features)
// ============================================================================

__global__ void scalar_prop_kernel(const float* __restrict__ tin,
                                   float* __restrict__ tout,
                                   const int* __restrict__ rp,
                                   const int2* __restrict__ epack, int N) {
    int n = blockIdx.x * blockDim.x + threadIdx.x;
    if (n >= N) return;
    float acc = 0.0f;
    int e1 = rp[n + 1];
    #pragma unroll 4
    for (int e = rp[n]; e < e1; ++e) {
        int2 md = __ldg(&epack[e]);
        acc += tin[md.x] * __int_as_float(md.y);
    }
    tout[n] = acc;
}

__global__ void combine1_kernel(const float* __restrict__ x,
                                const float* __restrict__ t1, const float* __restrict__ t2,
                                const float* __restrict__ t3, const float* __restrict__ t4,
                                const float* __restrict__ W1t, const float* __restrict__ b1,
                                float* __restrict__ H, int N) {
    int tid = blockIdx.x * blockDim.x + threadIdx.x;
    int n = tid >> 5;
    int l = tid & 31;
    if (n >= N) return;
    float v0 = __ldg(&x[n]),  v1 = __ldg(&t1[n]), v2 = __ldg(&t2[n]);
    float v3 = __ldg(&t3[n]), v4 = __ldg(&t4[n]);
    int j = 2 * l;
    float2 o  = *(const float2*)&b1[j];
    float2 w0 = *(const float2*)&W1t[0 * 64 + j];
    float2 w1 = *(const float2*)&W1t[1 * 64 + j];
    float2 w2 = *(const float2*)&W1t[2 * 64 + j];
    float2 w3 = *(const float2*)&W1t[3 * 64 + j];
    float2 w4 = *(const float2*)&W1t[4 * 64 + j];
    o.x += v0 * w0.x + v1 * w1.x + v2 * w2.x + v3 * w3.x + v4 * w4.x;
    o.y += v0 * w0.y + v1 * w1.y + v2 * w2.y + v3 * w3.y + v4 * w4.y;
    o.x = fmaxf(o.x, 0.0f);
    o.y = fmaxf(o.y, 0.0f);
    ((float2*)H)[n * 32 + l] = o;
}

// ============================================================================
// Pure gather prop: P = L̂ Tin
// ============================================================================

__global__ void prop_kernel(const float* __restrict__ Tin,
                            float* __restrict__ Pout,
                            const int* __restrict__ rp,
                            const int2* __restrict__ epack, int N) {
    const float4* Tin4 = (const float4*)Tin;
    int warp = threadIdx.x >> 5, lane = threadIdx.x & 31;
    int c = lane & 15, h = lane >> 4;
    int wpb = blockDim.x >> 5;
    for (int n = blockIdx.x * wpb + warp; n < N; n += gridDim.x * wpb) {
        int e0 = rp[n], e1 = rp[n + 1];
        float4 acc = make_float4(0.f, 0.f, 0.f, 0.f);
        #pragma unroll 4
        for (int e = e0 + h; e < e1; e += 2) {
            int2 md = __ldg(&epack[e]);
            float nm = __int_as_float(md.y);
            float4 v = Tin4[(size_t)md.x * 16 + c];
            acc.x += nm * v.x; acc.y += nm * v.y;
            acc.z += nm * v.z; acc.w += nm * v.w;
        }
        acc.x += __shfl_xor_sync(FULLMASK, acc.x, 16);
        acc.y += __shfl_xor_sync(FULLMASK, acc.y, 16);
        acc.z += __shfl_xor_sync(FULLMASK, acc.z, 16);
        acc.w += __shfl_xor_sync(FULLMASK, acc.w, 16);
        if (h == 0) ((float4*)Pout)[n * 16 + c] = acc;
    }
}

// ============================================================================
// GEMM pieces (f32x2 inner loop).  128x64 block tile, 8 rows x 4 cols / thread.
// ============================================================================

static constexpr int GEMMP_SMEM = (256 * 64 + 128 * 32) * 4;   // 81920
static constexpr int GEMMF_SMEM = (64 * 64 + 128 * 32) * 4;    // 32768

// partial: OUT = bias + A0@W0 + A1@W1 + A2@W2 + A3@W3   (Wflat = [256,64])
__global__ __launch_bounds__(256) void gemm_partial_kernel(
        const float* __restrict__ A0, const float* __restrict__ A1,
        const float* __restrict__ A2, const float* __restrict__ A3,
        const float* __restrict__ Wflat, const float* __restrict__ bias,
        float* __restrict__ OUT, int N) {
    extern __shared__ float smem[];
    float*  Bs  = smem;                 // [256][64]
    float*  As  = smem + 256 * 64;      // [128][32]
    float4* Bs4 = (float4*)Bs;
    const ulonglong2* Bs2 = (const ulonglong2*)Bs;
    float4* As4 = (float4*)As;

    for (int i = threadIdx.x; i < 4096; i += 256)
        Bs4[i] = ((const float4*)Wflat)[i];

    const int tid = threadIdx.x;
    const int rg = tid >> 4, cg = tid & 15;
    const int m0 = rg * 8;
    const int blockRow = blockIdx.x * 128;
    const float* bufs[4] = {A0, A1, A2, A3};

    unsigned long long accL[8], accH[8];
    #pragma unroll
    for (int r = 0; r < 8; ++r) { accL[r] = 0ull; accH[r] = 0ull; }

    const int lm   = tid >> 1;
    const int lcol = (tid & 1) * 16;
    const int grow = blockRow + lm;

    #pragma unroll
    for (int kc = 0; kc < 8; ++kc) {
        const float* src = bufs[kc >> 1] + ((kc & 1) << 5);
        __syncthreads();
        float4 v0, v1, v2, v3;
        if (grow < N) {
            const float4* s4 = (const float4*)(src + (size_t)grow * 64 + lcol);
            v0 = s4[0]; v1 = s4[1]; v2 = s4[2]; v3 = s4[3];
        } else v0 = v1 = v2 = v3 = make_float4(0.f, 0.f, 0.f, 0.f);
        int ab = lm * 8 + (lcol >> 2);
        As4[ab + 0] = v0; As4[ab + 1] = v1; As4[ab + 2] = v2; As4[ab + 3] = v3;
        __syncthreads();

        #pragma unroll
        for (int k4 = 0; k4 < 8; ++k4) {
            int kb = kc * 32 + k4 * 4;
            ulonglong2 b0 = Bs2[(kb + 0) * 16 + cg];
            ulonglong2 b1 = Bs2[(kb + 1) * 16 + cg];
            ulonglong2 b2 = Bs2[(kb + 2) * 16 + cg];
            ulonglong2 b3 = Bs2[(kb + 3) * 16 + cg];
            #pragma unroll
            for (int r = 0; r < 8; ++r) {
                float4 a = As4[(m0 + r) * 8 + k4];
                unsigned long long ax = pk2(a.x, a.x), ay = pk2(a.y, a.y);
                unsigned long long az = pk2(a.z, a.z), aw = pk2(a.w, a.w);
                fma2(accL[r], ax, b0.x); fma2(accH[r], ax, b0.y);
                fma2(accL[r], ay, b1.x); fma2(accH[r], ay, b1.y);
                fma2(accL[r], az, b2.x); fma2(accH[r], az, b2.y);
                fma2(accL[r], aw, b3.x); fma2(accH[r], aw, b3.y);
            }
        }
    }

    float4 bv = *(const float4*)&bias[cg * 4];
    #pragma unroll
    for (int r = 0; r < 8; ++r) {
        int row = blockRow + m0 + r;
        if (row < N) {
            float2 lo = upk2(accL[r]);
            float2 hi = upk2(accH[r]);
            ((float4*)OUT)[(size_t)row * 16 + cg] =
                make_float4(lo.x + bv.x, lo.y + bv.y, hi.x + bv.z, hi.y + bv.w);
        }
    }
}

// Shared mainloop for the final (A4-only, K=64) pieces.
template <bool FC>
__device__ __forceinline__ void gemm_final_body(
        const float* __restrict__ A4, const float* __restrict__ W4,
        const float* __restrict__ OUT,
        float* __restrict__ outH,                  // FC=false
        const float* __restrict__ Wfc, const float* __restrict__ bfc,
        float* __restrict__ y,                     // FC=true
        int N) {
    extern __shared__ float smem[];
    float*  Bs  = smem;                 // [64][64]
    float*  As  = smem + 64 * 64;       // [128][32]
    float4* Bs4 = (float4*)Bs;
    const ulonglong2* Bs2 = (const ulonglong2*)Bs;
    float4* As4 = (float4*)As;

    for (int i = threadIdx.x; i < 1024; i += 256)
        Bs4[i] = ((const float4*)W4)[i];

    const int tid = threadIdx.x;
    const int rg = tid >> 4, cg = tid & 15;
    const int m0 = rg * 8;
    const int blockRow = blockIdx.x * 128;

    unsigned long long accL[8], accH[8];
    #pragma unroll
    for (int r = 0; r < 8; ++r) { accL[r] = 0ull; accH[r] = 0ull; }

    const int lm   = tid >> 1;
    const int lcol = (tid & 1) * 16;
    const int grow = blockRow + lm;

    #pragma unroll
    for (int kc = 0; kc < 2; ++kc) {
        const float* src = A4 + kc * 32;
        __syncthreads();
        float4 v0, v1, v2, v3;
        if (grow < N) {
            const float4* s4 = (const float4*)(src + (size_t)grow * 64 + lcol);
            v0 = s4[0]; v1 = s4[1]; v2 = s4[2]; v3 = s4[3];
        } else v0 = v1 = v2 = v3 = make_float4(0.f, 0.f, 0.f, 0.f);
        int ab = lm * 8 + (lcol >> 2);
        As4[ab + 0] = v0; As4[ab + 1] = v1; As4[ab + 2] = v2; As4[ab + 3] = v3;
        __syncthreads();

        #pragma unroll
        for (int k4 = 0; k4 < 8; ++k4) {
            int kb = kc * 32 + k4 * 4;
            ulonglong2 b0 = Bs2[(kb + 0) * 16 + cg];
            ulonglong2 b1 = Bs2[(kb + 1) * 16 + cg];
            ulonglong2 b2 = Bs2[(kb + 2) * 16 + cg];
            ulonglong2 b3 = Bs2[(kb + 3) * 16 + cg];
            #pragma unroll
            for (int r = 0; r < 8; ++r) {
                float4 a = As4[(m0 + r) * 8 + k4];
                unsigned long long ax = pk2(a.x, a.x), ay = pk2(a.y, a.y);
                unsigned long long az = pk2(a.z, a.z), aw = pk2(a.w, a.w);
                fma2(accL[r], ax, b0.x); fma2(accH[r], ax, b0.y);
                fma2(accL[r], ay, b1.x); fma2(accH[r], ay, b1.y);
                fma2(accL[r], az, b2.x); fma2(accH[r], az, b2.y);
                fma2(accL[r], aw, b3.x); fma2(accH[r], aw, b3.y);
            }
        }
    }

    float4 wfc;
    float bb = 0.f;
    if (FC) { wfc = *(const float4*)&Wfc[cg * 4]; bb = __ldg(bfc); }

    #pragma unroll
    for (int r = 0; r < 8; ++r) {
        int row = blockRow + m0 + r;
        float2 lo = upk2(accL[r]);
        float2 hi = upk2(accH[r]);
        float4 ov = (row < N) ? ((const float4*)OUT)[(size_t)row * 16 + cg]
                              : make_float4(0.f, 0.f, 0.f, 0.f);
        float4 o = make_float4(fmaxf(lo.x + ov.x, 0.f), fmaxf(lo.y + ov.y, 0.f),
                               fmaxf(hi.x + ov.z, 0.f), fmaxf(hi.y + ov.w, 0.f));
        if (FC) {
            float p = o.x * wfc.x + o.y * wfc.y + o.z * wfc.z + o.w * wfc.w;
            p += __shfl_xor_sync(FULLMASK, p, 1);
            p += __shfl_xor_sync(FULLMASK, p, 2);
            p += __shfl_xor_sync(FULLMASK, p, 4);
            p += __shfl_xor_sync(FULLMASK, p, 8);
            if (cg == 0 && row < N) y[row] = p + bb;
        } else {
            if (row < N) ((float4*)outH)[(size_t)row * 16 + cg] = o;
        }
    }
}

__global__ __launch_bounds__(256) void gemm_final_kernel(
        const float* __restrict__ A4, const float* __restrict__ W4,
        const float* __restrict__ OUT, float* __restrict__ outH, int N) {
    gemm_final_body<false>(A4, W4, OUT, outH, nullptr, nullptr, nullptr, N);
}

__global__ __launch_bounds__(256) void gemm_final_fc_kernel(
        const float* __restrict__ A4, const float* __restrict__ W4,
        const float* __restrict__ OUT,
        const float* __restrict__ Wfc, const float* __restrict__ bfc,
        float* __restrict__ y, int N) {
    gemm_final_body<true>(A4, W4, OUT, nullptr, Wfc, bfc, y, N);
}

// ============================================================================
// Host launch
// ============================================================================

extern "C" void kernel_launch(void* const* d_in, const int* in_sizes, int n_in,
                              void* d_out, int out_size) {
    const float* x   = (const float*)d_in[0];
    const int*   ei  = (const int*)d_in[1];
    const float* W1  = (const float*)d_in[2];
    const float* b1  = (const float*)d_in[3];
    const float* W2  = (const float*)d_in[4];
    const float* b2  = (const float*)d_in[5];
    const float* W3  = (const float*)d_in[6];
    const float* b3  = (const float*)d_in[7];
    const float* Wfc = (const float*)d_in[8];
    const float* bfc = (const float*)d_in[9];
    float* out = (float*)d_out;

    const int N = in_sizes[0];
    const int E = in_sizes[1] / 2;

    int *deg, *cnt, *rp, *cursor, *bsum;
    int2* epack;
    float *dinv, *t1, *t2, *t3, *t4, *X0, *X1, *X2, *X3, *X4, *OUT, *W1t, *W2t, *W3t;
    cudaGetSymbolAddress((void**)&deg,   g_deg);
    cudaGetSymbolAddress((void**)&cnt,   g_cnt);
    cudaGetSymbolAddress((void**)&dinv,  g_dinv);
    cudaGetSymbolAddress((void**)&rp,    g_rp);
    cudaGetSymbolAddress((void**)&cursor,g_cursor);
    cudaGetSymbolAddress((void**)&bsum,  g_bsum);
    cudaGetSymbolAddress((void**)&epack, g_epack);
    cudaGetSymbolAddress((void**)&t1,    g_t1);
    cudaGetSymbolAddress((void**)&t2,    g_t2);
    cudaGetSymbolAddress((void**)&t3,    g_t3);
    cudaGetSymbolAddress((void**)&t4,    g_t4);
    cudaGetSymbolAddress((void**)&X0,    g_X0);
    cudaGetSymbolAddress((void**)&X1,    g_X1);
    cudaGetSymbolAddress((void**)&X2,    g_X2);
    cudaGetSymbolAddress((void**)&X3,    g_X3);
    cudaGetSymbolAddress((void**)&X4,    g_X4);
    cudaGetSymbolAddress((void**)&OUT,   g_OUT);
    cudaGetSymbolAddress((void**)&W1t,   g_W1t);
    cudaGetSymbolAddress((void**)&W2t,   g_W2t);
    cudaGetSymbolAddress((void**)&W3t,   g_W3t);

    static cudaStream_t s1 = nullptr;
    static cudaEvent_t evFork, evW, evP2, evG2, evP3, evG3;
    static bool init_done = false;
    if (!init_done) {
        cudaStreamCreateWithFlags(&s1, cudaStreamNonBlocking);
        cudaEventCreateWithFlags(&evFork, cudaEventDisableTiming);
        cudaEventCreateWithFlags(&evW,    cudaEventDisableTiming);
        cudaEventCreateWithFlags(&evP2,   cudaEventDisableTiming);
        cudaEventCreateWithFlags(&evG2,   cudaEventDisableTiming);
        cudaEventCreateWithFlags(&evP3,   cudaEventDisableTiming);
        cudaEventCreateWithFlags(&evG3,   cudaEventDisableTiming);
        cudaFuncSetAttribute(gemm_partial_kernel,
                             cudaFuncAttributeMaxDynamicSharedMemorySize, GEMMP_SMEM);
        cudaFuncSetAttribute(gemm_final_kernel,
                             cudaFuncAttributeMaxDynamicSharedMemorySize, GEMMF_SMEM);
        cudaFuncSetAttribute(gemm_final_fc_kernel,
                             cudaFuncAttributeMaxDynamicSharedMemorySize, GEMMF_SMEM);
        init_done = true;
    }

    const int EB = (E + 255) / 256;
    const int NB = (N + 255) / 256;
    const int nb1024 = (N + 1023) / 1024;
    const int PGRID = 1184;
    const int GB = (N + 127) / 128;

    // Fork side stream; wtrans runs there, overlapping preprocess.
    cudaEventRecord(evFork, 0);
    cudaStreamWaitEvent(s1, evFork, 0);
    wtrans_kernel<<<(64 + 8192 + 255) / 256, 256, 0, s1>>>(W1, W2, W3, W1t, W2t, W3t);
    cudaEventRecord(evW, s1);

    // --- preprocess (main stream) ---
    zero2_kernel<<<NB, 256>>>(deg, cnt, N);
    deg_hist_kernel<<<EB, 256>>>(ei, E, deg, cnt);
    scanb_dinv_kernel<<<nb1024, 1024>>>(cnt, deg, rp, bsum, dinv, N);
    scan_add_kernel<<<nb1024, 1024>>>(rp, cursor, bsum, nb1024, N);
    scatter_kernel<<<EB, 256>>>(ei, E, dinv, cursor, epack);

    // --- layer 1 ---
    scalar_prop_kernel<<<NB, 256>>>(x,  t1, rp, epack, N);
    scalar_prop_kernel<<<NB, 256>>>(t1, t2, rp, epack, N);
    scalar_prop_kernel<<<NB, 256>>>(t2, t3, rp, epack, N);
    scalar_prop_kernel<<<NB, 256>>>(t3, t4, rp, epack, N);
    cudaStreamWaitEvent(0, evW, 0);
    combine1_kernel<<<(N * 32 + 255) / 256, 256>>>(x, t1, t2, t3, t4, W1t, b1, X0, N);

    // --- layer 2 ---
    prop_kernel<<<PGRID, 256>>>(X0, X1, rp, epack, N);
    prop_kernel<<<PGRID, 256>>>(X1, X2, rp, epack, N);
    prop_kernel<<<PGRID, 256>>>(X2, X3, rp, epack, N);
    cudaEventRecord(evP2, 0);
    cudaStreamWaitEvent(s1, evP2, 0);
    gemm_partial_kernel<<<GB, 256, GEMMP_SMEM, s1>>>(X0, X1, X2, X3, W2t, b2, OUT, N);
    cudaEventRecord(evG2, s1);
    prop_kernel<<<PGRID, 256>>>(X3, X4, rp, epack, N);   // overlaps partial GEMM
    cudaStreamWaitEvent(0, evG2, 0);
    gemm_final_kernel<<<GB, 256, GEMMF_SMEM>>>(X4, W2t + 4 * 4096, OUT, X0, N);

    // --- layer 3 ---
    prop_kernel<<<PGRID, 256>>>(X0, X1, rp, epack, N);
    prop_kernel<<<PGRID, 256>>>(X1, X2, rp, epack, N);
    prop_kernel<<<PGRID, 256>>>(X2, X3, rp, epack, N);
    cudaEventRecord(evP3, 0);
    cudaStreamWaitEvent(s1, evP3, 0);
    gemm_partial_kernel<<<GB, 256, GEMMP_SMEM, s1>>>(X0, X1, X2, X3, W3t, b3, OUT, N);
    cudaEventRecord(evG3, s1);
    prop_kernel<<<PGRID, 256>>>(X3, X4, rp, epack, N);   // overlaps partial GEMM
    cudaStreamWaitEvent(0, evG3, 0);
    gemm_final_fc_kernel<<<GB, 256, GEMMF_SMEM>>>(X4, W3t + 4 * 4096, OUT, Wfc, bfc, out, N);
}

// round 8
// speedup vs baseline: 1.8267x; 1.1433x over previous
#include <cuda_runtime.h>
#include <cuda_fp16.h>

// ============================================================================
// ChebNet R8: Chebyshev basis (stable, original weights) + fp16 feature
// storage (all compute fp32). T0..T4 stored as __half [N,64] (128B rows).
//   out = [T0|T1|T2|T3|T4] @ Wflat + b,  Wflat = original W [320,64]
// ============================================================================

#define FULLMASK 0xffffffffu

static constexpr int NMAX = 131072;
static constexpr int EMAX = 2000000;
static constexpr int NBMAX = 128;

// ---- static device scratch ----
__device__ int    g_deg[NMAX];
__device__ int    g_cnt[NMAX];
__device__ float  g_dinv[NMAX];
__device__ int    g_rp[NMAX + 1];
__device__ int    g_cursor[NMAX];
__device__ int    g_bsum[NBMAX];
__device__ int2   g_epack[EMAX];
__device__ float  g_t1[NMAX], g_t2[NMAX], g_t3[NMAX], g_t4[NMAX];
__device__ __half g_X0[NMAX * 64];
__device__ __half g_X1[NMAX * 64];
__device__ __half g_X2[NMAX * 64];
__device__ __half g_X3[NMAX * 64];
__device__ __half g_X4[NMAX * 64];
__device__ float  g_OUT[NMAX * 64];

// ---- f32x2 packed FMA helpers ----
__device__ __forceinline__ unsigned long long pk2(float x, float y) {
    unsigned long long r;
    asm("mov.b64 %0, {%1, %2};" : "=l"(r) : "f"(x), "f"(y));
    return r;
}
__device__ __forceinline__ void fma2(unsigned long long& d,
                                     unsigned long long a, unsigned long long b) {
    asm("fma.rn.f32x2 %0, %1, %2, %0;" : "+l"(d) : "l"(a), "l"(b));
}
__device__ __forceinline__ float2 upk2(unsigned long long v) {
    float2 f;
    asm("mov.b64 {%0, %1}, %2;" : "=f"(f.x), "=f"(f.y) : "l"(v));
    return f;
}

// ============================================================================
// Preprocessing
// ============================================================================

__global__ void zero2_kernel(int* __restrict__ a, int* __restrict__ b, int N) {
    int i = blockIdx.x * blockDim.x + threadIdx.x;
    if (i < N) { a[i] = 0; b[i] = 0; }
}

__global__ void deg_hist_kernel(const int* __restrict__ ei, int E,
                                int* __restrict__ deg, int* __restrict__ cnt) {
    int e = blockIdx.x * blockDim.x + threadIdx.x;
    if (e < E) {
        atomicAdd(&deg[ei[e]], 1);
        atomicAdd(&cnt[ei[E + e]], 1);
    }
}

__global__ void scanb_dinv_kernel(const int* __restrict__ cnt,
                                  const int* __restrict__ deg,
                                  int* __restrict__ rp, int* __restrict__ bsum,
                                  float* __restrict__ dinv, int N) {
    __shared__ int s[1024];
    int idx = blockIdx.x * 1024 + threadIdx.x;
    int v = (idx < N) ? cnt[idx] : 0;
    s[threadIdx.x] = v;
    __syncthreads();
    for (int off = 1; off < 1024; off <<= 1) {
        int t = (threadIdx.x >= off) ? s[threadIdx.x - off] : 0;
        __syncthreads();
        s[threadIdx.x] += t;
        __syncthreads();
    }
    if (idx < N) {
        rp[idx] = s[threadIdx.x] - v;
        int d = deg[idx];
        dinv[idx] = (d > 0) ? rsqrtf((float)d) : 0.0f;
    }
    if (threadIdx.x == 1023) bsum[blockIdx.x] = s[1023];
}

__global__ void scan_add_kernel(int* __restrict__ rp, int* __restrict__ cursor,
                                const int* __restrict__ bsum, int nb, int N) {
    __shared__ int sb[NBMAX];
    int idx = blockIdx.x * 1024 + threadIdx.x;
    if (threadIdx.x < NBMAX)
        sb[threadIdx.x] = (threadIdx.x < nb) ? bsum[threadIdx.x] : 0;
    __syncthreads();
    for (int off = 1; off < NBMAX; off <<= 1) {
        int t = (threadIdx.x < NBMAX && threadIdx.x >= off) ? sb[threadIdx.x - off] : 0;
        __syncthreads();
        if (threadIdx.x < NBMAX) sb[threadIdx.x] += t;
        __syncthreads();
    }
    int soff = (blockIdx.x == 0) ? 0 : sb[blockIdx.x - 1];
    if (blockIdx.x == (unsigned)(gridDim.x - 1) && threadIdx.x == 0)
        rp[N] = sb[nb - 1];
    if (idx < N) {
        int r = rp[idx] + soff;
        rp[idx] = r;
        cursor[idx] = r;
    }
}

__global__ void scatter_kernel(const int* __restrict__ ei, int E,
                               const float* __restrict__ dinv,
                               int* __restrict__ cursor,
                               int2* __restrict__ epack) {
    int e = blockIdx.x * blockDim.x + threadIdx.x;
    if (e < E) {
        int s = ei[e];
        int d = ei[E + e];
        float nm = -(dinv[s] * dinv[d]);
        int pos = atomicAdd(&cursor[d], 1);
        epack[pos] = make_int2(s, __float_as_int(nm));
    }
}

// ============================================================================
// Layer 1 (scalar features, fp32, Chebyshev recurrence)
// ============================================================================

template <bool USE_PREV>
__global__ void scalar_prop_kernel(const float* __restrict__ tin,
                                   const float* __restrict__ tprev,
                                   float* __restrict__ tout,
                                   const int* __restrict__ rp,
                                   const int2* __restrict__ epack, int N) {
    int n = blockIdx.x * blockDim.x + threadIdx.x;
    if (n >= N) return;
    float acc = 0.0f;
    int e1 = rp[n + 1];
    #pragma unroll 4
    for (int e = rp[n]; e < e1; ++e) {
        int2 md = __ldg(&epack[e]);
        acc += tin[md.x] * __int_as_float(md.y);
    }
    tout[n] = USE_PREV ? (2.0f * acc - tprev[n]) : acc;
}

__global__ void combine1_kernel(const float* __restrict__ x,
                                const float* __restrict__ t1, const float* __restrict__ t2,
                                const float* __restrict__ t3, const float* __restrict__ t4,
                                const float* __restrict__ W1, const float* __restrict__ b1,
                                __half* __restrict__ H, int N) {
    int tid = blockIdx.x * blockDim.x + threadIdx.x;
    int n = tid >> 5;
    int l = tid & 31;
    if (n >= N) return;
    float v0 = __ldg(&x[n]),  v1 = __ldg(&t1[n]), v2 = __ldg(&t2[n]);
    float v3 = __ldg(&t3[n]), v4 = __ldg(&t4[n]);
    int j = 2 * l;
    float2 o  = *(const float2*)&b1[j];
    float2 w0 = *(const float2*)&W1[0 * 64 + j];
    float2 w1 = *(const float2*)&W1[1 * 64 + j];
    float2 w2 = *(const float2*)&W1[2 * 64 + j];
    float2 w3 = *(const float2*)&W1[3 * 64 + j];
    float2 w4 = *(const float2*)&W1[4 * 64 + j];
    o.x += v0 * w0.x + v1 * w1.x + v2 * w2.x + v3 * w3.x + v4 * w4.x;
    o.y += v0 * w0.y + v1 * w1.y + v2 * w2.y + v3 * w3.y + v4 * w4.y;
    o.x = fmaxf(o.x, 0.0f);
    o.y = fmaxf(o.y, 0.0f);
    ((__half2*)H)[n * 32 + l] = __floats2half2_rn(o.x, o.y);
}

// ============================================================================
// Chebyshev gather prop (fp16 rows, fp32 accumulate):
//   Tout = 2*L̂Tin - Tprev   (FIRST: Tout = L̂Tin)
// quarter-warp per edge (4 in flight), lane f owns features [8f, 8f+8).
// ============================================================================

template <bool FIRST>
__global__ void prop_cheb_h_kernel(const __half* __restrict__ Tin,
                                   const __half* __restrict__ Tprev,
                                   __half* __restrict__ Tout,
                                   const int* __restrict__ rp,
                                   const int2* __restrict__ epack, int N) {
    const float4* Tin4 = (const float4*)Tin;
    int warp = threadIdx.x >> 5, lane = threadIdx.x & 31;
    int q = lane >> 3;      // edge slot 0..3
    int f = lane & 7;       // feature octet
    int wpb = blockDim.x >> 5;
    for (int n = blockIdx.x * wpb + warp; n < N; n += gridDim.x * wpb) {
        int e0 = rp[n], e1 = rp[n + 1];
        float2 a0 = make_float2(0.f, 0.f), a1 = a0, a2 = a0, a3 = a0;
        #pragma unroll 4
        for (int e = e0 + q; e < e1; e += 4) {
            int2 md = __ldg(&epack[e]);
            float nm = __int_as_float(md.y);
            float4 v = Tin4[(size_t)md.x * 8 + f];
            float2 f0 = __half22float2(*(const __half2*)&v.x);
            float2 f1 = __half22float2(*(const __half2*)&v.y);
            float2 f2 = __half22float2(*(const __half2*)&v.z);
            float2 f3 = __half22float2(*(const __half2*)&v.w);
            a0.x += nm * f0.x; a0.y += nm * f0.y;
            a1.x += nm * f1.x; a1.y += nm * f1.y;
            a2.x += nm * f2.x; a2.y += nm * f2.y;
            a3.x += nm * f3.x; a3.y += nm * f3.y;
        }
        #pragma unroll
        for (int off = 8; off <= 16; off <<= 1) {
            a0.x += __shfl_xor_sync(FULLMASK, a0.x, off);
            a0.y += __shfl_xor_sync(FULLMASK, a0.y, off);
            a1.x += __shfl_xor_sync(FULLMASK, a1.x, off);
            a1.y += __shfl_xor_sync(FULLMASK, a1.y, off);
            a2.x += __shfl_xor_sync(FULLMASK, a2.x, off);
            a2.y += __shfl_xor_sync(FULLMASK, a2.y, off);
            a3.x += __shfl_xor_sync(FULLMASK, a3.x, off);
            a3.y += __shfl_xor_sync(FULLMASK, a3.y, off);
        }
        if (q == 0) {
            if (!FIRST) {
                float4 pv = ((const float4*)Tprev)[(size_t)n * 8 + f];
                float2 p0 = __half22float2(*(const __half2*)&pv.x);
                float2 p1 = __half22float2(*(const __half2*)&pv.y);
                float2 p2 = __half22float2(*(const __half2*)&pv.z);
                float2 p3 = __half22float2(*(const __half2*)&pv.w);
                a0.x = 2.f * a0.x - p0.x; a0.y = 2.f * a0.y - p0.y;
                a1.x = 2.f * a1.x - p1.x; a1.y = 2.f * a1.y - p1.y;
                a2.x = 2.f * a2.x - p2.x; a2.y = 2.f * a2.y - p2.y;
                a3.x = 2.f * a3.x - p3.x; a3.y = 2.f * a3.y - p3.y;
            }
            float4 st;
            ((__half2*)&st)[0] = __floats2half2_rn(a0.x, a0.y);
            ((__half2*)&st)[1] = __floats2half2_rn(a1.x, a1.y);
            ((__half2*)&st)[2] = __floats2half2_rn(a2.x, a2.y);
            ((__half2*)&st)[3] = __floats2half2_rn(a3.x, a3.y);
            ((float4*)Tout)[(size_t)n * 8 + f] = st;
        }
    }
}

// ============================================================================
// GEMM pieces (fp16 A staged->fp32 smem; f32x2 inner loop; original weights).
// ============================================================================

static constexpr int GEMMP_SMEM = (256 * 64 + 128 * 32) * 4;   // 81920
static constexpr int GEMMF_SMEM = (64 * 64 + 128 * 32) * 4;    // 32768

__device__ __forceinline__ void stage_a_h(const __half* __restrict__ src,
                                          float4* __restrict__ As4,
                                          int grow, int lm, int lcol, int N) {
    float4 v0, v1, v2, v3;
    if (grow < N) {
        const float4* s4 = (const float4*)(src + (size_t)grow * 64 + lcol);
        float4 r0 = s4[0];
        float4 r1 = s4[1];
        float2 p0 = __half22float2(*(const __half2*)&r0.x);
        float2 p1 = __half22float2(*(const __half2*)&r0.y);
        float2 p2 = __half22float2(*(const __half2*)&r0.z);
        float2 p3 = __half22float2(*(const __half2*)&r0.w);
        float2 p4 = __half22float2(*(const __half2*)&r1.x);
        float2 p5 = __half22float2(*(const __half2*)&r1.y);
        float2 p6 = __half22float2(*(const __half2*)&r1.z);
        float2 p7 = __half22float2(*(const __half2*)&r1.w);
        v0 = make_float4(p0.x, p0.y, p1.x, p1.y);
        v1 = make_float4(p2.x, p2.y, p3.x, p3.y);
        v2 = make_float4(p4.x, p4.y, p5.x, p5.y);
        v3 = make_float4(p6.x, p6.y, p7.x, p7.y);
    } else v0 = v1 = v2 = v3 = make_float4(0.f, 0.f, 0.f, 0.f);
    int ab = lm * 8 + (lcol >> 2);
    As4[ab + 0] = v0; As4[ab + 1] = v1; As4[ab + 2] = v2; As4[ab + 3] = v3;
}

// partial: OUT = bias + T0@W0 + .. + T3@W3   (Wflat = first [256,64] of W)
__global__ __launch_bounds__(256) void gemm_partial_kernel(
        const __half* __restrict__ A0, const __half* __restrict__ A1,
        const __half* __restrict__ A2, const __half* __restrict__ A3,
        const float* __restrict__ Wflat, const float* __restrict__ bias,
        float* __restrict__ OUT, int N) {
    extern __shared__ float smem[];
    float*  Bs  = smem;                 // [256][64]
    float*  As  = smem + 256 * 64;      // [128][32]
    float4* Bs4 = (float4*)Bs;
    const ulonglong2* Bs2 = (const ulonglong2*)Bs;
    float4* As4 = (float4*)As;

    for (int i = threadIdx.x; i < 4096; i += 256)
        Bs4[i] = ((const float4*)Wflat)[i];

    const int tid = threadIdx.x;
    const int rg = tid >> 4, cg = tid & 15;
    const int m0 = rg * 8;
    const int blockRow = blockIdx.x * 128;
    const __half* bufs[4] = {A0, A1, A2, A3};

    unsigned long long accL[8], accH[8];
    #pragma unroll
    for (int r = 0; r < 8; ++r) { accL[r] = 0ull; accH[r] = 0ull; }

    const int lm   = tid >> 1;
    const int lcol = (tid & 1) * 16;
    const int grow = blockRow + lm;

    #pragma unroll
    for (int kc = 0; kc < 8; ++kc) {
        const __half* src = bufs[kc >> 1] + ((kc & 1) << 5);
        __syncthreads();
        stage_a_h(src, As4, grow, lm, lcol, N);
        __syncthreads();

        #pragma unroll
        for (int k4 = 0; k4 < 8; ++k4) {
            int kb = kc * 32 + k4 * 4;
            ulonglong2 b0 = Bs2[(kb + 0) * 16 + cg];
            ulonglong2 b1 = Bs2[(kb + 1) * 16 + cg];
            ulonglong2 b2 = Bs2[(kb + 2) * 16 + cg];
            ulonglong2 b3 = Bs2[(kb + 3) * 16 + cg];
            #pragma unroll
            for (int r = 0; r < 8; ++r) {
                float4 a = As4[(m0 + r) * 8 + k4];
                unsigned long long ax = pk2(a.x, a.x), ay = pk2(a.y, a.y);
                unsigned long long az = pk2(a.z, a.z), aw = pk2(a.w, a.w);
                fma2(accL[r], ax, b0.x); fma2(accH[r], ax, b0.y);
                fma2(accL[r], ay, b1.x); fma2(accH[r], ay, b1.y);
                fma2(accL[r], az, b2.x); fma2(accH[r], az, b2.y);
                fma2(accL[r], aw, b3.x); fma2(accH[r], aw, b3.y);
            }
        }
    }

    float4 bv = *(const float4*)&bias[cg * 4];
    #pragma unroll
    for (int r = 0; r < 8; ++r) {
        int row = blockRow + m0 + r;
        if (row < N) {
            float2 lo = upk2(accL[r]);
            float2 hi = upk2(accH[r]);
            ((float4*)OUT)[(size_t)row * 16 + cg] =
                make_float4(lo.x + bv.x, lo.y + bv.y, hi.x + bv.z, hi.y + bv.w);
        }
    }
}

// final: h = relu(OUT + T4@W4); FC=false -> write fp16 H; FC=true -> y = h.Wfc+bfc
template <bool FC>
__device__ __forceinline__ void gemm_final_body(
        const __half* __restrict__ A4, const float* __restrict__ W4,
        const float* __restrict__ OUT,
        __half* __restrict__ outH,
        const float* __restrict__ Wfc, const float* __restrict__ bfc,
        float* __restrict__ y, int N) {
    extern __shared__ float smem[];
    float*  Bs  = smem;                 // [64][64]
    float*  As  = smem + 64 * 64;       // [128][32]
    float4* Bs4 = (float4*)Bs;
    const ulonglong2* Bs2 = (const ulonglong2*)Bs;
    float4* As4 = (float4*)As;

    for (int i = threadIdx.x; i < 1024; i += 256)
        Bs4[i] = ((const float4*)W4)[i];

    const int tid = threadIdx.x;
    const int rg = tid >> 4, cg = tid & 15;
    const int m0 = rg * 8;
    const int blockRow = blockIdx.x * 128;

    unsigned long long accL[8], accH[8];
    #pragma unroll
    for (int r = 0; r < 8; ++r) { accL[r] = 0ull; accH[r] = 0ull; }

    const int lm   = tid >> 1;
    const int lcol = (tid & 1) * 16;
    const int grow = blockRow + lm;

    #pragma unroll
    for (int kc = 0; kc < 2; ++kc) {
        const __half* src = A4 + kc * 32;
        __syncthreads();
        stage_a_h(src, As4, grow, lm, lcol, N);
        __syncthreads();

        #pragma unroll
        for (int k4 = 0; k4 < 8; ++k4) {
            int kb = kc * 32 + k4 * 4;
            ulonglong2 b0 = Bs2[(kb + 0) * 16 + cg];
            ulonglong2 b1 = Bs2[(kb + 1) * 16 + cg];
            ulonglong2 b2 = Bs2[(kb + 2) * 16 + cg];
            ulonglong2 b3 = Bs2[(kb + 3) * 16 + cg];
            #pragma unroll
            for (int r = 0; r < 8; ++r) {
                float4 a = As4[(m0 + r) * 8 + k4];
                unsigned long long ax = pk2(a.x, a.x), ay = pk2(a.y, a.y);
                unsigned long long az = pk2(a.z, a.z), aw = pk2(a.w, a.w);
                fma2(accL[r], ax, b0.x); fma2(accH[r], ax, b0.y);
                fma2(accL[r], ay, b1.x); fma2(accH[r], ay, b1.y);
                fma2(accL[r], az, b2.x); fma2(accH[r], az, b2.y);
                fma2(accL[r], aw, b3.x); fma2(accH[r], aw, b3.y);
            }
        }
    }

    float4 wfc;
    float bb = 0.f;
    if (FC) { wfc = *(const float4*)&Wfc[cg * 4]; bb = __ldg(bfc); }

    #pragma unroll
    for (int r = 0; r < 8; ++r) {
        int row = blockRow + m0 + r;
        float2 lo = upk2(accL[r]);
        float2 hi = upk2(accH[r]);
        float4 ov = (row < N) ? ((const float4*)OUT)[(size_t)row * 16 + cg]
                              : make_float4(0.f, 0.f, 0.f, 0.f);
        float4 o = make_float4(fmaxf(lo.x + ov.x, 0.f), fmaxf(lo.y + ov.y, 0.f),
                               fmaxf(hi.x + ov.z, 0.f), fmaxf(hi.y + ov.w, 0.f));
        if (FC) {
            float p = o.x * wfc.x + o.y * wfc.y + o.z * wfc.z + o.w * wfc.w;
            p += __shfl_xor_sync(FULLMASK, p, 1);
            p += __shfl_xor_sync(FULLMASK, p, 2);
            p += __shfl_xor_sync(FULLMASK, p, 4);
            p += __shfl_xor_sync(FULLMASK, p, 8);
            if (cg == 0 && row < N) y[row] = p + bb;
        } else if (row < N) {
            float2 st;
            ((__half2*)&st)[0] = __floats2half2_rn(o.x, o.y);
            ((__half2*)&st)[1] = __floats2half2_rn(o.z, o.w);
            ((float2*)outH)[(size_t)row * 16 + cg] = st;
        }
    }
}

__global__ __launch_bounds__(256) void gemm_final_kernel(
        const __half* __restrict__ A4, const float* __restrict__ W4,
        const float* __restrict__ OUT, __half* __restrict__ outH, int N) {
    gemm_final_body<false>(A4, W4, OUT, outH, nullptr, nullptr, nullptr, N);
}

__global__ __launch_bounds__(256) void gemm_final_fc_kernel(
        const __half* __restrict__ A4, const float* __restrict__ W4,
        const float* __restrict__ OUT,
        const float* __restrict__ Wfc, const float* __restrict__ bfc,
        float* __restrict__ y, int N) {
    gemm_final_body<true>(A4, W4, OUT, nullptr, Wfc, bfc, y, N);
}

// ============================================================================
// Host launch
// ============================================================================

extern "C" void kernel_launch(void* const* d_in, const int* in_sizes, int n_in,
                              void* d_out, int out_size) {
    const float* x   = (const float*)d_in[0];
    const int*   ei  = (const int*)d_in[1];
    const float* W1  = (const float*)d_in[2];
    const float* b1  = (const float*)d_in[3];
    const float* W2  = (const float*)d_in[4];
    const float* b2  = (const float*)d_in[5];
    const float* W3  = (const float*)d_in[6];
    const float* b3  = (const float*)d_in[7];
    const float* Wfc = (const float*)d_in[8];
    const float* bfc = (const float*)d_in[9];
    float* out = (float*)d_out;

    const int N = in_sizes[0];
    const int E = in_sizes[1] / 2;

    int *deg, *cnt, *rp, *cursor, *bsum;
    int2* epack;
    float *dinv, *t1, *t2, *t3, *t4, *OUT;
    __half *X0, *X1, *X2, *X3, *X4;
    cudaGetSymbolAddress((void**)&deg,   g_deg);
    cudaGetSymbolAddress((void**)&cnt,   g_cnt);
    cudaGetSymbolAddress((void**)&dinv,  g_dinv);
    cudaGetSymbolAddress((void**)&rp,    g_rp);
    cudaGetSymbolAddress((void**)&cursor,g_cursor);
    cudaGetSymbolAddress((void**)&bsum,  g_bsum);
    cudaGetSymbolAddress((void**)&epack, g_epack);
    cudaGetSymbolAddress((void**)&t1,    g_t1);
    cudaGetSymbolAddress((void**)&t2,    g_t2);
    cudaGetSymbolAddress((void**)&t3,    g_t3);
    cudaGetSymbolAddress((void**)&t4,    g_t4);
    cudaGetSymbolAddress((void**)&X0,    g_X0);
    cudaGetSymbolAddress((void**)&X1,    g_X1);
    cudaGetSymbolAddress((void**)&X2,    g_X2);
    cudaGetSymbolAddress((void**)&X3,    g_X3);
    cudaGetSymbolAddress((void**)&X4,    g_X4);
    cudaGetSymbolAddress((void**)&OUT,   g_OUT);

    static cudaStream_t s1 = nullptr;
    static cudaEvent_t evFork, evP2, evG2, evP3, evG3;
    static bool init_done = false;
    if (!init_done) {
        cudaStreamCreateWithFlags(&s1, cudaStreamNonBlocking);
        cudaEventCreateWithFlags(&evFork, cudaEventDisableTiming);
        cudaEventCreateWithFlags(&evP2,   cudaEventDisableTiming);
        cudaEventCreateWithFlags(&evG2,   cudaEventDisableTiming);
        cudaEventCreateWithFlags(&evP3,   cudaEventDisableTiming);
        cudaEventCreateWithFlags(&evG3,   cudaEventDisableTiming);
        cudaFuncSetAttribute(gemm_partial_kernel,
                             cudaFuncAttributeMaxDynamicSharedMemorySize, GEMMP_SMEM);
        cudaFuncSetAttribute(gemm_final_kernel,
                             cudaFuncAttributeMaxDynamicSharedMemorySize, GEMMF_SMEM);
        cudaFuncSetAttribute(gemm_final_fc_kernel,
                             cudaFuncAttributeMaxDynamicSharedMemorySize, GEMMF_SMEM);
        init_done = true;
    }

    const int EB = (E + 255) / 256;
    const int NB = (N + 255) / 256;
    const int nb1024 = (N + 1023) / 1024;
    const int PGRID = 1184;
    const int GB = (N + 127) / 128;

    // --- preprocess ---
    zero2_kernel<<<NB, 256>>>(deg, cnt, N);
    deg_hist_kernel<<<EB, 256>>>(ei, E, deg, cnt);
    scanb_dinv_kernel<<<nb1024, 1024>>>(cnt, deg, rp, bsum, dinv, N);
    scan_add_kernel<<<nb1024, 1024>>>(rp, cursor, bsum, nb1024, N);
    scatter_kernel<<<EB, 256>>>(ei, E, dinv, cursor, epack);

    // --- layer 1 (Chebyshev scalar) ---
    scalar_prop_kernel<false><<<NB, 256>>>(x,  nullptr, t1, rp, epack, N);
    scalar_prop_kernel<true ><<<NB, 256>>>(t1, x,       t2, rp, epack, N);
    scalar_prop_kernel<true ><<<NB, 256>>>(t2, t1,      t3, rp, epack, N);
    scalar_prop_kernel<true ><<<NB, 256>>>(t3, t2,      t4, rp, epack, N);
    combine1_kernel<<<(N * 32 + 255) / 256, 256>>>(x, t1, t2, t3, t4, W1, b1, X0, N);

    // --- layer 2: T0=X0; T1..T4 -> X1..X4 (Chebyshev); GEMM -> X0 ---
    prop_cheb_h_kernel<true ><<<PGRID, 256>>>(X0, nullptr, X1, rp, epack, N);
    prop_cheb_h_kernel<false><<<PGRID, 256>>>(X1, X0,      X2, rp, epack, N);
    prop_cheb_h_kernel<false><<<PGRID, 256>>>(X2, X1,      X3, rp, epack, N);
    cudaEventRecord(evP2, 0);
    cudaStreamWaitEvent(s1, evP2, 0);
    gemm_partial_kernel<<<GB, 256, GEMMP_SMEM, s1>>>(X0, X1, X2, X3, W2, b2, OUT, N);
    cudaEventRecord(evG2, s1);
    prop_cheb_h_kernel<false><<<PGRID, 256>>>(X3, X2, X4, rp, epack, N);  // overlaps
    cudaStreamWaitEvent(0, evG2, 0);
    gemm_final_kernel<<<GB, 256, GEMMF_SMEM>>>(X4, W2 + 4 * 4096, OUT, X0, N);

    // --- layer 3 ---
    prop_cheb_h_kernel<true ><<<PGRID, 256>>>(X0, nullptr, X1, rp, epack, N);
    prop_cheb_h_kernel<false><<<PGRID, 256>>>(X1, X0,      X2, rp, epack, N);
    prop_cheb_h_kernel<false><<<PGRID, 256>>>(X2, X1,      X3, rp, epack, N);
    cudaEventRecord(evP3, 0);
    cudaStreamWaitEvent(s1, evP3, 0);
    gemm_partial_kernel<<<GB, 256, GEMMP_SMEM, s1>>>(X0, X1, X2, X3, W3, b3, OUT, N);
    cudaEventRecord(evG3, s1);
    prop_cheb_h_kernel<false><<<PGRID, 256>>>(X3, X2, X4, rp, epack, N);  // overlaps
    cudaStreamWaitEvent(0, evG3, 0);
    gemm_final_fc_kernel<<<GB, 256, GEMMF_SMEM>>>(X4, W3 + 4 * 4096, OUT, Wfc, bfc, out, N);
}